// round 11
// baseline (speedup 1.0000x reference)
#include <cuda_runtime.h>

#define NN 50000
#define EE 500000
#define NB 8
#define NPGX 6250
#define FDIM 266   // 10 + 4*64
#define OUTC 532

// ---------------- scratch (device globals: no runtime allocation allowed) ----------------
__device__ float    g_F[(size_t)NN * FDIM];   // concat features
__device__ float    g_H[(size_t)NN * 64];     // current h
__device__ float    g_T[(size_t)NN * 128];    // MLP hidden
__device__ float    g_NP[(size_t)NN * 384];   // [ni | nj | nproj]
__device__ float    g_hatt[(size_t)NN * 128];
__device__ float    g_e[(size_t)EE * 2];      // logits, then exp()
__device__ unsigned g_m[NN * 2];              // mono-encoded segment max
__device__ float    g_s[NN * 2];              // softmax denom
__device__ float    g_gmax[NB * FDIM];
__device__ float    g_TeP[3][7 * 128];        // etype table (+ (rc_b+rp_b)@Wf + egat_bias)
__device__ float    g_Tr[3][31 * 128];
__device__ float    g_Arc[3][2 * 128];
__device__ float    g_Arp[3][3 * 128];

// ---------------- helpers ----------------
__device__ __forceinline__ void ffma2(unsigned long long& d, unsigned long long a, unsigned long long b) {
    asm("fma.rn.f32x2 %0, %1, %2, %0;" : "+l"(d) : "l"(a), "l"(b));
}
__device__ __forceinline__ unsigned long long dup2(float x) {
    unsigned long long r; asm("mov.b64 %0, {%1, %1};" : "=l"(r) : "f"(x)); return r;
}
__device__ __forceinline__ float2 unpk(unsigned long long v) {
    float2 r; asm("mov.b64 {%0, %1}, %2;" : "=f"(r.x), "=f"(r.y) : "l"(v)); return r;
}
__device__ __forceinline__ void red_add_v4(float* p, float a, float b, float c, float d) {
    asm volatile("red.global.add.v4.f32 [%0], {%1,%2,%3,%4};"
                 :: "l"(p), "f"(a), "f"(b), "f"(c), "f"(d) : "memory");
}
__device__ __forceinline__ void red_add_v2(float* p, float a, float b) {
    asm volatile("red.global.add.v2.f32 [%0], {%1,%2};"
                 :: "l"(p), "f"(a), "f"(b) : "memory");
}
__device__ __forceinline__ unsigned mono(float f) {
    unsigned u = __float_as_uint(f);
    return u ^ (((unsigned)((int)u >> 31)) | 0x80000000u);
}
__device__ __forceinline__ float demono(unsigned u) {
    unsigned v = (u & 0x80000000u) ? (u ^ 0x80000000u) : ~u;
    return __uint_as_float(v);
}

// ---------------- zero per-layer scratch ----------------
__global__ void k_zero() {
    int i = blockIdx.x * blockDim.x + threadIdx.x;          // 1.6M threads
    ((float4*)g_hatt)[i] = make_float4(0.f, 0.f, 0.f, 0.f);
    if (i < (NN * 2) / 4) {
        ((uint4*)g_m)[i]  = make_uint4(0u, 0u, 0u, 0u);
        ((float4*)g_s)[i] = make_float4(0.f, 0.f, 0.f, 0.f);
    }
}

// ---------------- feature MLP: h0 = relu(feat@W0+b0)@W1+b1 ; writes F[:,0:74] ----------------
__global__ __launch_bounds__(128) void k_feat_mlp(const float* __restrict__ feat,
                                                  const float* __restrict__ W0, const float* __restrict__ b0,
                                                  const float* __restrict__ W1, const float* __restrict__ b1) {
    __shared__ float sW0[640], sb0[64], sW1[4096], sb1[64];
    int tid = threadIdx.x;
    for (int i = tid; i < 640;  i += 128) sW0[i] = W0[i];
    for (int i = tid; i < 4096; i += 128) sW1[i] = W1[i];
    if (tid < 64) { sb0[tid] = b0[tid]; sb1[tid] = b1[tid]; }
    __syncthreads();
    int row = blockIdx.x * 128 + tid;
    if (row >= NN) return;
    float x[10];
#pragma unroll
    for (int k = 0; k < 10; k++) x[k] = feat[(size_t)row * 10 + k];
#pragma unroll
    for (int k = 0; k < 10; k++) g_F[(size_t)row * FDIM + k] = x[k];
    float hid[64];
    for (int j = 0; j < 64; j++) {
        float a = sb0[j];
#pragma unroll
        for (int k = 0; k < 10; k++) a += x[k] * sW0[k * 64 + j];
        hid[j] = fmaxf(a, 0.f);
    }
    for (int j = 0; j < 64; j++) {
        float a = sb1[j];
#pragma unroll
        for (int k = 0; k < 64; k++) a += hid[k] * sW1[k * 64 + j];
        g_H[(size_t)row * 64 + j] = a;
        g_F[(size_t)row * FDIM + 10 + j] = a;
    }
}

// ---------------- per-layer edge tables: fold W_fij into tiny lookup tables ----------------
__global__ __launch_bounds__(256) void k_tables(const float* __restrict__ etype_emb, const float* __restrict__ rid_emb,
                                                const float* __restrict__ rc_W, const float* __restrict__ rc_b,
                                                const float* __restrict__ rp_W, const float* __restrict__ rp_b,
                                                const float* __restrict__ W_fij, const float* __restrict__ egat_bias) {
    int l = blockIdx.x;
    const float* Wf = W_fij + (size_t)l * 64 * 128;
    __shared__ float rows[43][64];
    __shared__ float cb[64];
    int tid = threadIdx.x;
    if (tid < 64) cb[tid] = rc_b[tid] + rp_b[tid];
    __syncthreads();
    for (int i = tid; i < 7 * 64;  i += 256) rows[i / 64][i % 64]      = etype_emb[i] + cb[i % 64];
    for (int i = tid; i < 31 * 64; i += 256) rows[7 + i / 64][i % 64]  = rid_emb[i];
    for (int i = tid; i < 2 * 64;  i += 256) rows[38 + i / 64][i % 64] = rc_W[i];
    for (int i = tid; i < 3 * 64;  i += 256) rows[40 + i / 64][i % 64] = rp_W[i];
    __syncthreads();
    for (int idx = tid; idx < 43 * 128; idx += 256) {
        int r = idx >> 7, o = idx & 127;
        float a = 0.f;
#pragma unroll
        for (int k = 0; k < 64; k++) a += rows[r][k] * Wf[k * 128 + o];
        if (r < 7)       g_TeP[l][r * 128 + o] = a + egat_bias[l * 128 + o];
        else if (r < 38) g_Tr[l][(r - 7) * 128 + o] = a;
        else if (r < 40) g_Arc[l][(r - 38) * 128 + o] = a;
        else             g_Arp[l][(r - 40) * 128 + o] = a;
    }
}

// ---------------- f32x2 GEMM, occupancy-tuned ----------------
// BM=64 rows/block, 256 threads, micro-tile 4 rows x TN cols (TN = BN/16).
// Columns split into NG groups of 4 (group g at g*64 + tx*4) -> conflict-free LDS.128.
// gridDim.y selects among up to 3 B matrices (shared A), output col offset y*BN.
template<int K, int BN>
__global__ __launch_bounds__(256, 3) void k_gemm(const float* __restrict__ A, int lda,
                                                 const float* __restrict__ B0,
                                                 const float* __restrict__ B1,
                                                 const float* __restrict__ B2,
                                                 const float* __restrict__ bias,
                                                 float* C, int ldc,
                                                 int do_relu,
                                                 const float* res,
                                                 float* Fout, int fcol,
                                                 int nrows) {
    constexpr int KC = 32, NG = BN / 64;   // NG in {1,2}
    __shared__ float As[KC][64];
    __shared__ float Bs[KC][BN];
    int tid = threadIdx.x;
    int ty = tid >> 4, tx = tid & 15;      // ty 0..15 (4 rows each), tx 0..15 (4 cols/group)
    int r0 = ty * 4;
    int rbase = blockIdx.x * 64;
    const float* B = (blockIdx.y == 0) ? B0 : (blockIdx.y == 1) ? B1 : B2;
    int ccol = blockIdx.y * BN;

    unsigned long long acc[4][NG][2];
#pragma unroll
    for (int i = 0; i < 4; i++)
#pragma unroll
        for (int g = 0; g < NG; g++) { acc[i][g][0] = 0ull; acc[i][g][1] = 0ull; }

    for (int kk = 0; kk < K; kk += KC) {
        // A tile: 64 rows x 32 k = 512 float4 slots; row fastest -> conflict-free STS
#pragma unroll
        for (int i = 0; i < 2; i++) {
            int slot = tid + i * 256;
            int row = slot & 63, q = slot >> 6;          // q 0..7
            float4 v = make_float4(0.f, 0.f, 0.f, 0.f);
            int gr = rbase + row;
            if (gr < nrows) v = *(const float4*)(A + (size_t)gr * lda + kk + q * 4);
            As[q * 4 + 0][row] = v.x; As[q * 4 + 1][row] = v.y;
            As[q * 4 + 2][row] = v.z; As[q * 4 + 3][row] = v.w;
        }
        // B tile: 32 x BN; consecutive lanes -> contiguous -> conflict-free
#pragma unroll
        for (int i = 0; i < (KC * BN / 4) / 256; i++) {
            int slot = tid + i * 256;
            int kr = slot / (BN / 4), q = slot % (BN / 4);
            *(float4*)&Bs[kr][q * 4] = *(const float4*)(B + (size_t)(kk + kr) * BN + q * 4);
        }
        __syncthreads();
#pragma unroll
        for (int k = 0; k < KC; k++) {
            float4 av = *(const float4*)&As[k][r0];
            unsigned long long aa[4];
            aa[0] = dup2(av.x); aa[1] = dup2(av.y); aa[2] = dup2(av.z); aa[3] = dup2(av.w);
            unsigned long long bb[NG][2];
#pragma unroll
            for (int g = 0; g < NG; g++) {
                ulonglong2 t = *(const ulonglong2*)&Bs[k][g * 64 + tx * 4];
                bb[g][0] = t.x; bb[g][1] = t.y;
            }
#pragma unroll
            for (int i = 0; i < 4; i++)
#pragma unroll
                for (int g = 0; g < NG; g++) {
                    ffma2(acc[i][g][0], aa[i], bb[g][0]);
                    ffma2(acc[i][g][1], aa[i], bb[g][1]);
                }
        }
        __syncthreads();
    }
#pragma unroll
    for (int i = 0; i < 4; i++) {
        int gr = rbase + r0 + i;
        if (gr >= nrows) continue;
#pragma unroll
        for (int g = 0; g < NG; g++)
#pragma unroll
            for (int p = 0; p < 2; p++) {
                float2 v = unpk(acc[i][g][p]);
                int j = g * 64 + tx * 4 + p * 2;
                if (bias) { v.x += bias[j]; v.y += bias[j + 1]; }
                if (do_relu) { v.x = fmaxf(v.x, 0.f); v.y = fmaxf(v.y, 0.f); }
                if (res) { float2 rv = *(const float2*)(res + (size_t)gr * 64 + j); v.x += rv.x; v.y += rv.y; }
                *(float2*)(C + (size_t)gr * ldc + ccol + j) = v;
                if (Fout) *(float2*)(Fout + (size_t)gr * FDIM + fcol + j) = v;
            }
    }
}

// ---------------- attention logits + segment max (one warp per edge) ----------------
__global__ __launch_bounds__(256) void k_attn(int l,
                                              const int* __restrict__ src, const int* __restrict__ dst,
                                              const int* __restrict__ etype, const int* __restrict__ rid,
                                              const float* __restrict__ att_rc, const float* __restrict__ att_rp,
                                              const float* __restrict__ attnv) {
    int lane = threadIdx.x & 31;
    int gw = (blockIdx.x * blockDim.x + threadIdx.x) >> 5;
    int nw = (gridDim.x * blockDim.x) >> 5;
    int c = lane * 4;
    const float* Arc = g_Arc[l]; const float* Arp = g_Arp[l];
    const float* TeP = g_TeP[l]; const float* Trt = g_Tr[l];
    float4 arc0 = *(const float4*)(Arc + c);
    float4 arc1 = *(const float4*)(Arc + 128 + c);
    float4 arp0 = *(const float4*)(Arp + c);
    float4 arp1 = *(const float4*)(Arp + 128 + c);
    float4 arp2 = *(const float4*)(Arp + 256 + c);
    float4 at   = *(const float4*)(attnv + c);
    for (int e = gw; e < EE; e += nw) {
        int s  = __ldg(src + e),   d  = __ldg(dst + e);
        int et = __ldg(etype + e), rr = __ldg(rid + e);
        float2 rc = __ldg((const float2*)att_rc + e);
        const float* rpp = att_rp + (size_t)e * 3;
        float rp0 = __ldg(rpp), rp1 = __ldg(rpp + 1), rp2 = __ldg(rpp + 2);
        float4 te = *(const float4*)(TeP + et * 128 + c);
        float4 tr = *(const float4*)(Trt + rr * 128 + c);
        float4 ni = *(const float4*)(g_NP + (size_t)s * 384 + c);
        float4 nj = *(const float4*)(g_NP + (size_t)d * 384 + 128 + c);
        float fx = ni.x + nj.x + te.x + tr.x + rc.x * arc0.x + rc.y * arc1.x + rp0 * arp0.x + rp1 * arp1.x + rp2 * arp2.x;
        float fy = ni.y + nj.y + te.y + tr.y + rc.x * arc0.y + rc.y * arc1.y + rp0 * arp0.y + rp1 * arp1.y + rp2 * arp2.y;
        float fz = ni.z + nj.z + te.z + tr.z + rc.x * arc0.z + rc.y * arc1.z + rp0 * arp0.z + rp1 * arp1.z + rp2 * arp2.z;
        float fw = ni.w + nj.w + te.w + tr.w + rc.x * arc0.w + rc.y * arc1.w + rp0 * arp0.w + rp1 * arp1.w + rp2 * arp2.w;
        float p;
        p  = (fx > 0.f ? fx : 0.2f * fx) * at.x;
        p += (fy > 0.f ? fy : 0.2f * fy) * at.y;
        p += (fz > 0.f ? fz : 0.2f * fz) * at.z;
        p += (fw > 0.f ? fw : 0.2f * fw) * at.w;
        p += __shfl_xor_sync(0xffffffffu, p, 1);
        p += __shfl_xor_sync(0xffffffffu, p, 2);
        p += __shfl_xor_sync(0xffffffffu, p, 4);
        p += __shfl_xor_sync(0xffffffffu, p, 8);
        if ((lane & 15) == 0) {
            int h = lane >> 4;
            g_e[(size_t)e * 2 + h] = p;
            atomicMax(&g_m[(size_t)d * 2 + h], mono(p));
        }
    }
}

// ---------------- exp + segment sum ----------------
__global__ __launch_bounds__(256) void k_expsum(const int* __restrict__ dst) {
    int e = blockIdx.x * blockDim.x + threadIdx.x;
    if (e >= EE) return;
    int d = __ldg(dst + e);
    float2 ev = ((const float2*)g_e)[e];
    uint2 mu = *((const uint2*)g_m + d);
    float x0 = __expf(ev.x - demono(mu.x));
    float x1 = __expf(ev.y - demono(mu.y));
    ((float2*)g_e)[e] = make_float2(x0, x1);
    red_add_v2(&g_s[(size_t)d * 2], x0, x1);
}

// ---------------- message passing: h_att[dst] += alpha * nproj[src] (one warp per edge) ----------------
__global__ __launch_bounds__(256) void k_msg(const int* __restrict__ src, const int* __restrict__ dst) {
    int lane = threadIdx.x & 31;
    int gw = (blockIdx.x * blockDim.x + threadIdx.x) >> 5;
    int nw = (gridDim.x * blockDim.x) >> 5;
    int c = lane * 4;
    for (int e = gw; e < EE; e += nw) {
        int s = __ldg(src + e), d = __ldg(dst + e);
        float2 ex = __ldg((const float2*)g_e + e);
        float2 ss = __ldg((const float2*)g_s + d);
        float a0 = __fdividef(ex.x, ss.x + 1e-9f);
        float a1 = __fdividef(ex.y, ss.y + 1e-9f);
        float a = (lane < 16) ? a0 : a1;
        float4 np = *(const float4*)(g_NP + (size_t)s * 384 + 256 + c);
        red_add_v4(g_hatt + (size_t)d * 128 + c, a * np.x, a * np.y, a * np.z, a * np.w);
    }
}

// ---------------- graph max pooling ----------------
__global__ __launch_bounds__(512) void k_pool() {
    int chunk = blockIdx.x;            // 0..4 (64 cols each)
    int g = blockIdx.y;                // 0..7
    int tx = threadIdx.x & 63;
    int ty = threadIdx.x >> 6;         // 0..7
    int col = chunk * 64 + tx;
    float v = -3.4e38f;
    if (col < FDIM) {
        const float* base = g_F + (size_t)g * NPGX * FDIM + col;
        for (int r = ty; r < NPGX; r += 8) v = fmaxf(v, base[(size_t)r * FDIM]);
    }
    __shared__ float red[8][64];
    red[ty][tx] = v;
    __syncthreads();
    if (ty == 0 && col < FDIM) {
#pragma unroll
        for (int t = 1; t < 8; t++) v = fmaxf(v, red[t][tx]);
        g_gmax[g * FDIM + col] = v;
    }
}

// ---------------- output assembly: [features | graph_rep] ----------------
__global__ __launch_bounds__(256) void k_out(float2* __restrict__ out) {
    int idx = blockIdx.x * blockDim.x + threadIdx.x;        // float2 index
    const int TOT = NN * (OUTC / 2);                        // 13,300,000
    if (idx >= TOT) return;
    int c2 = idx % (OUTC / 2);
    int rn = idx / (OUTC / 2);
    int g = rn / NPGX;
    float2 v = (c2 < FDIM / 2) ? ((const float2*)g_F)[(size_t)rn * (FDIM / 2) + c2]
                               : ((const float2*)g_gmax)[(size_t)g * (FDIM / 2) + (c2 - FDIM / 2)];
    out[idx] = v;
}

// ---------------- host ----------------
extern "C" void kernel_launch(void* const* d_in, const int* in_sizes, int n_in,
                              void* d_out, int out_size) {
    (void)in_sizes; (void)n_in; (void)out_size;
    const float* feat      = (const float*)d_in[0];
    const float* att_rc    = (const float*)d_in[1];
    const float* att_rp    = (const float*)d_in[2];
    const float* etype_emb = (const float*)d_in[3];
    const float* rid_emb   = (const float*)d_in[4];
    const float* rc_W      = (const float*)d_in[5];
    const float* rc_b      = (const float*)d_in[6];
    const float* rp_W      = (const float*)d_in[7];
    const float* rp_b      = (const float*)d_in[8];
    const float* fe_W0     = (const float*)d_in[9];
    const float* fe_b0     = (const float*)d_in[10];
    const float* fe_W1     = (const float*)d_in[11];
    const float* fe_b1     = (const float*)d_in[12];
    const float* W_ni      = (const float*)d_in[13];
    const float* W_nj      = (const float*)d_in[14];
    const float* W_fij     = (const float*)d_in[15];
    const float* W_node    = (const float*)d_in[16];
    const float* attn      = (const float*)d_in[17];
    const float* egat_bias = (const float*)d_in[18];
    const float* Wm0       = (const float*)d_in[19];
    const float* bm0       = (const float*)d_in[20];
    const float* Wm1       = (const float*)d_in[21];
    const float* bm1       = (const float*)d_in[22];
    const int*   src       = (const int*)d_in[23];
    const int*   dst       = (const int*)d_in[24];
    const int*   etype     = (const int*)d_in[25];
    const int*   rid       = (const int*)d_in[26];

    float *pH, *pT, *pNP, *phatt, *pF;
    cudaGetSymbolAddress((void**)&pH,    g_H);
    cudaGetSymbolAddress((void**)&pT,    g_T);
    cudaGetSymbolAddress((void**)&pNP,   g_NP);
    cudaGetSymbolAddress((void**)&phatt, g_hatt);
    cudaGetSymbolAddress((void**)&pF,    g_F);

    const int GB64 = (NN + 63) / 64;   // 782 blocks of 64 rows

    k_feat_mlp<<<(NN + 127) / 128, 128>>>(feat, fe_W0, fe_b0, fe_W1, fe_b1);
    k_tables<<<3, 256>>>(etype_emb, rid_emb, rc_W, rc_b, rp_W, rp_b, W_fij, egat_bias);

    for (int l = 0; l < 3; l++) {
        k_zero<<<(NN * 128 / 4) / 256, 256>>>();
        // fused: NP[:,0:384] = H @ [W_ni | W_nj | W_node]
        k_gemm<64, 128><<<dim3(GB64, 3), 256>>>(pH, 64,
                                                W_ni + (size_t)l * 64 * 128,
                                                W_nj + (size_t)l * 64 * 128,
                                                W_node + (size_t)l * 64 * 128,
                                                nullptr, pNP, 384, 0, nullptr, nullptr, 0, NN);
        k_attn<<<1184, 256>>>(l, src, dst, etype, rid, att_rc, att_rp, attn + (size_t)l * 128);
        k_expsum<<<(EE + 255) / 256, 256>>>(dst);
        k_msg<<<1184, 256>>>(src, dst);
        k_gemm<128, 128><<<dim3(GB64, 1), 256>>>(phatt, 128,
                                                 Wm0 + (size_t)l * 128 * 128, nullptr, nullptr,
                                                 bm0 + (size_t)l * 128,
                                                 pT, 128, 1, nullptr, nullptr, 0, NN);
        k_gemm<128, 64><<<dim3(GB64, 1), 256>>>(pT, 128,
                                                Wm1 + (size_t)l * 128 * 64, nullptr, nullptr,
                                                bm1 + (size_t)l * 64,
                                                pH, 64, 0, pH, pF, 10 + 64 * (l + 1), NN);
    }
    k_pool<<<dim3(5, NB), 512>>>();
    k_out<<<(NN * (OUTC / 2) + 255) / 256, 256>>>((float2*)d_out);
}

// round 12
// speedup vs baseline: 1.4836x; 1.4836x over previous
#include <cuda_runtime.h>

#define NN 50000
#define EE 500000
#define NB 8
#define NPGX 6250
#define FDIM 266   // 10 + 4*64
#define OUTC 532

// ---------------- scratch (device globals: no runtime allocation allowed) ----------------
__device__ float    g_F[(size_t)NN * FDIM];   // concat features
__device__ float    g_H[(size_t)NN * 64];     // current h
__device__ float    g_T[(size_t)NN * 128];    // MLP hidden / feat-MLP hidden
__device__ float    g_NP[(size_t)NN * 384];   // [ni | nj | nproj]
__device__ float    g_hatt[(size_t)NN * 128];
__device__ float    g_e[(size_t)EE * 2];      // logits, then exp()
__device__ unsigned g_m[NN * 2];              // mono-encoded segment max
__device__ float    g_s[NN * 2];              // softmax denom
__device__ unsigned g_gmaxU[NB * FDIM];       // mono-encoded graph max
__device__ float    g_TeP[3][7 * 128];        // etype table (+ (rc_b+rp_b)@Wf + egat_bias)
__device__ float    g_Tr[3][31 * 128];
__device__ float    g_Arc[3][2 * 128];
__device__ float    g_Arp[3][3 * 128];

// ---------------- helpers ----------------
__device__ __forceinline__ void ffma2(unsigned long long& d, unsigned long long a, unsigned long long b) {
    asm("fma.rn.f32x2 %0, %1, %2, %0;" : "+l"(d) : "l"(a), "l"(b));
}
__device__ __forceinline__ unsigned long long dup2(float x) {
    unsigned long long r; asm("mov.b64 %0, {%1, %1};" : "=l"(r) : "f"(x)); return r;
}
__device__ __forceinline__ float2 unpk(unsigned long long v) {
    float2 r; asm("mov.b64 {%0, %1}, %2;" : "=f"(r.x), "=f"(r.y) : "l"(v)); return r;
}
__device__ __forceinline__ void red_add_v4(float* p, float a, float b, float c, float d) {
    asm volatile("red.global.add.v4.f32 [%0], {%1,%2,%3,%4};"
                 :: "l"(p), "f"(a), "f"(b), "f"(c), "f"(d) : "memory");
}
__device__ __forceinline__ void red_add_v2(float* p, float a, float b) {
    asm volatile("red.global.add.v2.f32 [%0], {%1,%2};"
                 :: "l"(p), "f"(a), "f"(b) : "memory");
}
__device__ __forceinline__ unsigned mono(float f) {
    unsigned u = __float_as_uint(f);
    return u ^ (((unsigned)((int)u >> 31)) | 0x80000000u);
}
__device__ __forceinline__ float demono(unsigned u) {
    unsigned v = (u & 0x80000000u) ? (u ^ 0x80000000u) : ~u;
    return __uint_as_float(v);
}

// ---------------- feature MLP stage 1: T = relu(feat@W0+b0) ; copies feat -> F[:,0:10] ----------------
__global__ __launch_bounds__(128) void k_feat1(const float* __restrict__ feat,
                                               const float* __restrict__ W0, const float* __restrict__ b0) {
    __shared__ float sW0[640], sb0[64];
    int tid = threadIdx.x;
    for (int i = tid; i < 640; i += 128) sW0[i] = W0[i];
    if (tid < 64) sb0[tid] = b0[tid];
    __syncthreads();
    int row = blockIdx.x * 128 + tid;
    if (row >= NN) return;
    float x[10];
#pragma unroll
    for (int k = 0; k < 10; k++) x[k] = feat[(size_t)row * 10 + k];
#pragma unroll
    for (int k = 0; k < 10; k++) g_F[(size_t)row * FDIM + k] = x[k];
    for (int j = 0; j < 64; j++) {
        float a = sb0[j];
#pragma unroll
        for (int k = 0; k < 10; k++) a += x[k] * sW0[k * 64 + j];
        g_T[(size_t)row * 128 + j] = fmaxf(a, 0.f);   // note ldc handled at call: use lda=128? -> store stride 128
    }
}

// ---------------- per-layer edge tables: fold W_fij into tiny lookup tables ----------------
__global__ __launch_bounds__(256) void k_tables(const float* __restrict__ etype_emb, const float* __restrict__ rid_emb,
                                                const float* __restrict__ rc_W, const float* __restrict__ rc_b,
                                                const float* __restrict__ rp_W, const float* __restrict__ rp_b,
                                                const float* __restrict__ W_fij, const float* __restrict__ egat_bias) {
    int l = blockIdx.x;
    const float* Wf = W_fij + (size_t)l * 64 * 128;
    __shared__ float rows[43][64];
    __shared__ float cb[64];
    int tid = threadIdx.x;
    if (tid < 64) cb[tid] = rc_b[tid] + rp_b[tid];
    __syncthreads();
    for (int i = tid; i < 7 * 64;  i += 256) rows[i / 64][i % 64]      = etype_emb[i] + cb[i % 64];
    for (int i = tid; i < 31 * 64; i += 256) rows[7 + i / 64][i % 64]  = rid_emb[i];
    for (int i = tid; i < 2 * 64;  i += 256) rows[38 + i / 64][i % 64] = rc_W[i];
    for (int i = tid; i < 3 * 64;  i += 256) rows[40 + i / 64][i % 64] = rp_W[i];
    __syncthreads();
    for (int idx = tid; idx < 43 * 128; idx += 256) {
        int r = idx >> 7, o = idx & 127;
        float a = 0.f;
#pragma unroll
        for (int k = 0; k < 64; k++) a += rows[r][k] * Wf[k * 128 + o];
        if (r < 7)       g_TeP[l][r * 128 + o] = a + egat_bias[l * 128 + o];
        else if (r < 38) g_Tr[l][(r - 7) * 128 + o] = a;
        else if (r < 40) g_Arc[l][(r - 38) * 128 + o] = a;
        else             g_Arp[l][(r - 40) * 128 + o] = a;
    }
}

// ---------------- f32x2 GEMM: BM=128, 8x8 micro-tile (8x4 for BN=64), occ 2 ----------------
// gridDim.y selects among up to 3 B matrices (shared A); output col offset y*BN.
template<int K, int BN>
__global__ __launch_bounds__(256, 2) void k_gemm(const float* __restrict__ A, int lda,
                                                 const float* __restrict__ B0,
                                                 const float* __restrict__ B1,
                                                 const float* __restrict__ B2,
                                                 const float* __restrict__ bias,
                                                 float* C, int ldc,
                                                 int do_relu,
                                                 const float* res,
                                                 float* Fout, int fcol,
                                                 int nrows) {
    constexpr int BM = 128, KC = 32, NG = BN / 64;   // NG in {1,2}
    __shared__ float As[KC][BM];
    __shared__ float Bs[KC][BN];
    int tid = threadIdx.x;
    int ty = tid >> 4, tx = tid & 15;      // ty 0..15 (8 rows each), tx 0..15 (4 cols/group)
    int r0 = ty * 8;
    int rbase = blockIdx.x * BM;
    const float* B = (blockIdx.y == 0) ? B0 : (blockIdx.y == 1) ? B1 : B2;
    int ccol = blockIdx.y * BN;

    unsigned long long acc[8][NG][2];
#pragma unroll
    for (int i = 0; i < 8; i++)
#pragma unroll
        for (int g = 0; g < NG; g++) { acc[i][g][0] = 0ull; acc[i][g][1] = 0ull; }

    for (int kk = 0; kk < K; kk += KC) {
        // A tile: 128 rows x 32 k = 1024 float4 slots; row fastest -> conflict-free STS
#pragma unroll
        for (int i = 0; i < 4; i++) {
            int slot = tid + i * 256;
            int row = slot & 127, q = slot >> 7;          // q 0..7
            float4 v = make_float4(0.f, 0.f, 0.f, 0.f);
            int gr = rbase + row;
            if (gr < nrows) v = *(const float4*)(A + (size_t)gr * lda + kk + q * 4);
            As[q * 4 + 0][row] = v.x; As[q * 4 + 1][row] = v.y;
            As[q * 4 + 2][row] = v.z; As[q * 4 + 3][row] = v.w;
        }
        // B tile: 32 x BN; consecutive lanes -> contiguous -> conflict-free
#pragma unroll
        for (int i = 0; i < (KC * BN / 4) / 256; i++) {
            int slot = tid + i * 256;
            int kr = slot / (BN / 4), q = slot % (BN / 4);
            *(float4*)&Bs[kr][q * 4] = *(const float4*)(B + (size_t)(kk + kr) * BN + q * 4);
        }
        __syncthreads();
#pragma unroll
        for (int k = 0; k < KC; k++) {
            float4 a0 = *(const float4*)&As[k][r0];
            float4 a1 = *(const float4*)&As[k][r0 + 4];
            unsigned long long aa[8];
            aa[0] = dup2(a0.x); aa[1] = dup2(a0.y); aa[2] = dup2(a0.z); aa[3] = dup2(a0.w);
            aa[4] = dup2(a1.x); aa[5] = dup2(a1.y); aa[6] = dup2(a1.z); aa[7] = dup2(a1.w);
            unsigned long long bb[NG][2];
#pragma unroll
            for (int g = 0; g < NG; g++) {
                ulonglong2 t = *(const ulonglong2*)&Bs[k][g * 64 + tx * 4];
                bb[g][0] = t.x; bb[g][1] = t.y;
            }
#pragma unroll
            for (int i = 0; i < 8; i++)
#pragma unroll
                for (int g = 0; g < NG; g++) {
                    ffma2(acc[i][g][0], aa[i], bb[g][0]);
                    ffma2(acc[i][g][1], aa[i], bb[g][1]);
                }
        }
        __syncthreads();
    }
#pragma unroll
    for (int i = 0; i < 8; i++) {
        int gr = rbase + r0 + i;
        if (gr >= nrows) continue;
#pragma unroll
        for (int g = 0; g < NG; g++)
#pragma unroll
            for (int p = 0; p < 2; p++) {
                float2 v = unpk(acc[i][g][p]);
                int j = g * 64 + tx * 4 + p * 2;
                if (bias) { v.x += bias[j]; v.y += bias[j + 1]; }
                if (do_relu) { v.x = fmaxf(v.x, 0.f); v.y = fmaxf(v.y, 0.f); }
                if (res) { float2 rv = *(const float2*)(res + (size_t)gr * 64 + j); v.x += rv.x; v.y += rv.y; }
                *(float2*)(C + (size_t)gr * ldc + ccol + j) = v;
                if (Fout) *(float2*)(Fout + (size_t)gr * FDIM + fcol + j) = v;
            }
    }
}

// ---------------- attention logits + segment max (one warp per edge) ----------------
__global__ __launch_bounds__(256) void k_attn(int l,
                                              const int* __restrict__ src, const int* __restrict__ dst,
                                              const int* __restrict__ etype, const int* __restrict__ rid,
                                              const float* __restrict__ att_rc, const float* __restrict__ att_rp,
                                              const float* __restrict__ attnv) {
    int lane = threadIdx.x & 31;
    int gw = (blockIdx.x * blockDim.x + threadIdx.x) >> 5;
    int nw = (gridDim.x * blockDim.x) >> 5;
    int c = lane * 4;
    const float* Arc = g_Arc[l]; const float* Arp = g_Arp[l];
    const float* TeP = g_TeP[l]; const float* Trt = g_Tr[l];
    float4 arc0 = *(const float4*)(Arc + c);
    float4 arc1 = *(const float4*)(Arc + 128 + c);
    float4 arp0 = *(const float4*)(Arp + c);
    float4 arp1 = *(const float4*)(Arp + 128 + c);
    float4 arp2 = *(const float4*)(Arp + 256 + c);
    float4 at   = *(const float4*)(attnv + c);
    for (int e = gw; e < EE; e += nw) {
        int s  = __ldg(src + e),   d  = __ldg(dst + e);
        int et = __ldg(etype + e), rr = __ldg(rid + e);
        float2 rc = __ldg((const float2*)att_rc + e);
        const float* rpp = att_rp + (size_t)e * 3;
        float rp0 = __ldg(rpp), rp1 = __ldg(rpp + 1), rp2 = __ldg(rpp + 2);
        float4 te = *(const float4*)(TeP + et * 128 + c);
        float4 tr = *(const float4*)(Trt + rr * 128 + c);
        float4 ni = *(const float4*)(g_NP + (size_t)s * 384 + c);
        float4 nj = *(const float4*)(g_NP + (size_t)d * 384 + 128 + c);
        float fx = ni.x + nj.x + te.x + tr.x + rc.x * arc0.x + rc.y * arc1.x + rp0 * arp0.x + rp1 * arp1.x + rp2 * arp2.x;
        float fy = ni.y + nj.y + te.y + tr.y + rc.x * arc0.y + rc.y * arc1.y + rp0 * arp0.y + rp1 * arp1.y + rp2 * arp2.y;
        float fz = ni.z + nj.z + te.z + tr.z + rc.x * arc0.z + rc.y * arc1.z + rp0 * arp0.z + rp1 * arp1.z + rp2 * arp2.z;
        float fw = ni.w + nj.w + te.w + tr.w + rc.x * arc0.w + rc.y * arc1.w + rp0 * arp0.w + rp1 * arp1.w + rp2 * arp2.w;
        float p;
        p  = (fx > 0.f ? fx : 0.2f * fx) * at.x;
        p += (fy > 0.f ? fy : 0.2f * fy) * at.y;
        p += (fz > 0.f ? fz : 0.2f * fz) * at.z;
        p += (fw > 0.f ? fw : 0.2f * fw) * at.w;
        p += __shfl_xor_sync(0xffffffffu, p, 1);
        p += __shfl_xor_sync(0xffffffffu, p, 2);
        p += __shfl_xor_sync(0xffffffffu, p, 4);
        p += __shfl_xor_sync(0xffffffffu, p, 8);
        if ((lane & 15) == 0) {
            int h = lane >> 4;
            g_e[(size_t)e * 2 + h] = p;
            atomicMax(&g_m[(size_t)d * 2 + h], mono(p));
        }
    }
}

// ---------------- exp + segment sum ----------------
__global__ __launch_bounds__(256) void k_expsum(const int* __restrict__ dst) {
    int e = blockIdx.x * blockDim.x + threadIdx.x;
    if (e >= EE) return;
    int d = __ldg(dst + e);
    float2 ev = ((const float2*)g_e)[e];
    uint2 mu = *((const uint2*)g_m + d);
    float x0 = __expf(ev.x - demono(mu.x));
    float x1 = __expf(ev.y - demono(mu.y));
    ((float2*)g_e)[e] = make_float2(x0, x1);
    red_add_v2(&g_s[(size_t)d * 2], x0, x1);
}

// ---------------- message passing: h_att[dst] += alpha * nproj[src] (one warp per edge) ----------------
__global__ __launch_bounds__(256) void k_msg(const int* __restrict__ src, const int* __restrict__ dst) {
    int lane = threadIdx.x & 31;
    int gw = (blockIdx.x * blockDim.x + threadIdx.x) >> 5;
    int nw = (gridDim.x * blockDim.x) >> 5;
    int c = lane * 4;
    for (int e = gw; e < EE; e += nw) {
        int s = __ldg(src + e), d = __ldg(dst + e);
        float2 ex = __ldg((const float2*)g_e + e);
        float2 ss = __ldg((const float2*)g_s + d);
        float a0 = __fdividef(ex.x, ss.x + 1e-9f);
        float a1 = __fdividef(ex.y, ss.y + 1e-9f);
        float a = (lane < 16) ? a0 : a1;
        float4 np = *(const float4*)(g_NP + (size_t)s * 384 + 256 + c);
        red_add_v4(g_hatt + (size_t)d * 128 + c, a * np.x, a * np.y, a * np.z, a * np.w);
    }
}

// ---------------- graph max pooling: coalesced row-streaming + mono atomicMax ----------------
__global__ __launch_bounds__(256) void k_pool() {
    int g = blockIdx.y;                     // graph 0..7
    int chunk = blockIdx.x;                 // row chunk 0..24 (250 rows each)
    int t = threadIdx.x;
    int r_lo = chunk * 250, r_hi = r_lo + 250;
    float v0 = -3.4e38f, v1 = -3.4e38f;
    const float* base = g_F + (size_t)g * NPGX * FDIM;
    for (int r = r_lo; r < r_hi; r++) {
        const float* row = base + (size_t)r * FDIM;
        v0 = fmaxf(v0, row[t]);
        if (t < FDIM - 256) v1 = fmaxf(v1, row[256 + t]);
    }
    atomicMax(&g_gmaxU[g * FDIM + t], mono(v0));
    if (t < FDIM - 256) atomicMax(&g_gmaxU[g * FDIM + 256 + t], mono(v1));
}

// ---------------- output assembly: [features | graph_rep] ----------------
__global__ __launch_bounds__(256) void k_out(float2* __restrict__ out) {
    int idx = blockIdx.x * blockDim.x + threadIdx.x;        // float2 index
    const int TOT = NN * (OUTC / 2);                        // 13,300,000
    if (idx >= TOT) return;
    int c2 = idx % (OUTC / 2);
    int rn = idx / (OUTC / 2);
    int g = rn / NPGX;
    float2 v;
    if (c2 < FDIM / 2) {
        v = ((const float2*)g_F)[(size_t)rn * (FDIM / 2) + c2];
    } else {
        int c = (c2 - FDIM / 2) * 2;
        v.x = demono(g_gmaxU[g * FDIM + c]);
        v.y = demono(g_gmaxU[g * FDIM + c + 1]);
    }
    out[idx] = v;
}

// ---------------- host ----------------
extern "C" void kernel_launch(void* const* d_in, const int* in_sizes, int n_in,
                              void* d_out, int out_size) {
    (void)in_sizes; (void)n_in; (void)out_size;
    const float* feat      = (const float*)d_in[0];
    const float* att_rc    = (const float*)d_in[1];
    const float* att_rp    = (const float*)d_in[2];
    const float* etype_emb = (const float*)d_in[3];
    const float* rid_emb   = (const float*)d_in[4];
    const float* rc_W      = (const float*)d_in[5];
    const float* rc_b      = (const float*)d_in[6];
    const float* rp_W      = (const float*)d_in[7];
    const float* rp_b      = (const float*)d_in[8];
    const float* fe_W0     = (const float*)d_in[9];
    const float* fe_b0     = (const float*)d_in[10];
    const float* fe_W1     = (const float*)d_in[11];
    const float* fe_b1     = (const float*)d_in[12];
    const float* W_ni      = (const float*)d_in[13];
    const float* W_nj      = (const float*)d_in[14];
    const float* W_fij     = (const float*)d_in[15];
    const float* W_node    = (const float*)d_in[16];
    const float* attn      = (const float*)d_in[17];
    const float* egat_bias = (const float*)d_in[18];
    const float* Wm0       = (const float*)d_in[19];
    const float* bm0       = (const float*)d_in[20];
    const float* Wm1       = (const float*)d_in[21];
    const float* bm1       = (const float*)d_in[22];
    const int*   src       = (const int*)d_in[23];
    const int*   dst       = (const int*)d_in[24];
    const int*   etype     = (const int*)d_in[25];
    const int*   rid       = (const int*)d_in[26];

    float *pH, *pT, *pNP, *phatt, *pF;
    unsigned *pm, *pgmax;
    float *ps;
    cudaGetSymbolAddress((void**)&pH,    g_H);
    cudaGetSymbolAddress((void**)&pT,    g_T);
    cudaGetSymbolAddress((void**)&pNP,   g_NP);
    cudaGetSymbolAddress((void**)&phatt, g_hatt);
    cudaGetSymbolAddress((void**)&pF,    g_F);
    cudaGetSymbolAddress((void**)&pm,    g_m);
    cudaGetSymbolAddress((void**)&ps,    g_s);
    cudaGetSymbolAddress((void**)&pgmax, g_gmaxU);

    const int GB = (NN + 127) / 128;   // 391 blocks of 128 rows

    k_feat1<<<GB, 128>>>(feat, fe_W0, fe_b0);
    k_tables<<<3, 256>>>(etype_emb, rid_emb, rc_W, rc_b, rp_W, rp_b, W_fij, egat_bias);
    // h0 = T@W1 + b1 ; also writes F[:,10:74]
    k_gemm<64, 64><<<dim3(GB, 1), 256>>>(pT, 128, fe_W1, nullptr, nullptr, fe_b1,
                                         pH, 64, 0, nullptr, pF, 10, NN);

    for (int l = 0; l < 3; l++) {
        cudaMemsetAsync(phatt, 0, (size_t)NN * 128 * sizeof(float));
        cudaMemsetAsync(pm,    0, (size_t)NN * 2 * sizeof(unsigned));
        cudaMemsetAsync(ps,    0, (size_t)NN * 2 * sizeof(float));
        // fused: NP[:,0:384] = H @ [W_ni | W_nj | W_node]
        k_gemm<64, 128><<<dim3(GB, 3), 256>>>(pH, 64,
                                              W_ni + (size_t)l * 64 * 128,
                                              W_nj + (size_t)l * 64 * 128,
                                              W_node + (size_t)l * 64 * 128,
                                              nullptr, pNP, 384, 0, nullptr, nullptr, 0, NN);
        k_attn<<<1184, 256>>>(l, src, dst, etype, rid, att_rc, att_rp, attn + (size_t)l * 128);
        k_expsum<<<(EE + 255) / 256, 256>>>(dst);
        k_msg<<<1184, 256>>>(src, dst);
        k_gemm<128, 128><<<dim3(GB, 1), 256>>>(phatt, 128,
                                               Wm0 + (size_t)l * 128 * 128, nullptr, nullptr,
                                               bm0 + (size_t)l * 128,
                                               pT, 128, 1, nullptr, nullptr, 0, NN);
        k_gemm<128, 64><<<dim3(GB, 1), 256>>>(pT, 128,
                                              Wm1 + (size_t)l * 128 * 64, nullptr, nullptr,
                                              bm1 + (size_t)l * 64,
                                              pH, 64, 0, pH, pF, 10 + 64 * (l + 1), NN);
    }
    cudaMemsetAsync(pgmax, 0, (size_t)NB * FDIM * sizeof(unsigned));
    k_pool<<<dim3(25, NB), 256>>>();
    k_out<<<(NN * (OUTC / 2) + 255) / 256, 256>>>((float2*)d_out);
}

// round 13
// speedup vs baseline: 1.8759x; 1.2644x over previous
#include <cuda_runtime.h>

#define NN 50000
#define EE 500000
#define NB 8
#define NPGX 6250
#define FDIM 266   // 10 + 4*64
#define OUTC 532

// ---------------- scratch (device globals: no runtime allocation allowed) ----------------
__device__ float    g_F[(size_t)NN * FDIM];   // concat features
__device__ float    g_H[(size_t)NN * 64];     // current h
__device__ float    g_T[(size_t)NN * 128];    // MLP hidden / feat-MLP hidden
__device__ float    g_NP[(size_t)NN * 384];   // [ni | nj | nproj]
__device__ float    g_hatt[(size_t)NN * 128]; // UNNORMALIZED sum of ex*nproj[src]
__device__ float    g_s[NN * 2];              // softmax denom (sum of ex per head)
__device__ unsigned g_gmaxU[NB * FDIM];       // mono-encoded graph max
__device__ float    g_TeP[3][7 * 128];        // etype table (+ (rc_b+rp_b)@Wf + egat_bias)
__device__ float    g_Tr[3][31 * 128];
__device__ float    g_Arc[3][2 * 128];
__device__ float    g_Arp[3][3 * 128];

// ---------------- helpers ----------------
__device__ __forceinline__ void ffma2(unsigned long long& d, unsigned long long a, unsigned long long b) {
    asm("fma.rn.f32x2 %0, %1, %2, %0;" : "+l"(d) : "l"(a), "l"(b));
}
__device__ __forceinline__ unsigned long long dup2(float x) {
    unsigned long long r; asm("mov.b64 %0, {%1, %1};" : "=l"(r) : "f"(x)); return r;
}
__device__ __forceinline__ float2 unpk(unsigned long long v) {
    float2 r; asm("mov.b64 {%0, %1}, %2;" : "=f"(r.x), "=f"(r.y) : "l"(v)); return r;
}
__device__ __forceinline__ void red_add_v4(float* p, float a, float b, float c, float d) {
    asm volatile("red.global.add.v4.f32 [%0], {%1,%2,%3,%4};"
                 :: "l"(p), "f"(a), "f"(b), "f"(c), "f"(d) : "memory");
}
__device__ __forceinline__ void red_add_v2(float* p, float a, float b) {
    asm volatile("red.global.add.v2.f32 [%0], {%1,%2};"
                 :: "l"(p), "f"(a), "f"(b) : "memory");
}
__device__ __forceinline__ unsigned mono(float f) {
    unsigned u = __float_as_uint(f);
    return u ^ (((unsigned)((int)u >> 31)) | 0x80000000u);
}
__device__ __forceinline__ float demono(unsigned u) {
    unsigned v = (u & 0x80000000u) ? (u ^ 0x80000000u) : ~u;
    return __uint_as_float(v);
}

// ---------------- feature MLP stage 1: T = relu(feat@W0+b0) ; copies feat -> F[:,0:10] ----------------
__global__ __launch_bounds__(128) void k_feat1(const float* __restrict__ feat,
                                               const float* __restrict__ W0, const float* __restrict__ b0) {
    __shared__ float sW0[640], sb0[64];
    int tid = threadIdx.x;
    for (int i = tid; i < 640; i += 128) sW0[i] = W0[i];
    if (tid < 64) sb0[tid] = b0[tid];
    __syncthreads();
    int row = blockIdx.x * 128 + tid;
    if (row >= NN) return;
    float x[10];
#pragma unroll
    for (int k = 0; k < 10; k++) x[k] = feat[(size_t)row * 10 + k];
#pragma unroll
    for (int k = 0; k < 10; k++) g_F[(size_t)row * FDIM + k] = x[k];
    for (int j = 0; j < 64; j++) {
        float a = sb0[j];
#pragma unroll
        for (int k = 0; k < 10; k++) a += x[k] * sW0[k * 64 + j];
        g_T[(size_t)row * 128 + j] = fmaxf(a, 0.f);
    }
}

// ---------------- per-layer edge tables: fold W_fij into tiny lookup tables ----------------
__global__ __launch_bounds__(256) void k_tables(const float* __restrict__ etype_emb, const float* __restrict__ rid_emb,
                                                const float* __restrict__ rc_W, const float* __restrict__ rc_b,
                                                const float* __restrict__ rp_W, const float* __restrict__ rp_b,
                                                const float* __restrict__ W_fij, const float* __restrict__ egat_bias) {
    int l = blockIdx.x;
    const float* Wf = W_fij + (size_t)l * 64 * 128;
    __shared__ float rows[43][64];
    __shared__ float cb[64];
    int tid = threadIdx.x;
    if (tid < 64) cb[tid] = rc_b[tid] + rp_b[tid];
    __syncthreads();
    for (int i = tid; i < 7 * 64;  i += 256) rows[i / 64][i % 64]      = etype_emb[i] + cb[i % 64];
    for (int i = tid; i < 31 * 64; i += 256) rows[7 + i / 64][i % 64]  = rid_emb[i];
    for (int i = tid; i < 2 * 64;  i += 256) rows[38 + i / 64][i % 64] = rc_W[i];
    for (int i = tid; i < 3 * 64;  i += 256) rows[40 + i / 64][i % 64] = rp_W[i];
    __syncthreads();
    for (int idx = tid; idx < 43 * 128; idx += 256) {
        int r = idx >> 7, o = idx & 127;
        float a = 0.f;
#pragma unroll
        for (int k = 0; k < 64; k++) a += rows[r][k] * Wf[k * 128 + o];
        if (r < 7)       g_TeP[l][r * 128 + o] = a + egat_bias[l * 128 + o];
        else if (r < 38) g_Tr[l][(r - 7) * 128 + o] = a;
        else if (r < 40) g_Arc[l][(r - 38) * 128 + o] = a;
        else             g_Arp[l][(r - 40) * 128 + o] = a;
    }
}

// ---------------- f32x2 GEMM: BM=128, 8x8 micro-tile (8x4 for BN=64), occ 2 ----------------
// gridDim.y selects among up to 3 B matrices (shared A); output col offset y*BN.
// rowscale (optional, float2 per row): A row r, cols [0,64) scaled by 1/(sc.x+1e-9),
// cols [64,128) by 1/(sc.y+1e-9)  -> folds softmax normalization into the Wm0 GEMM.
template<int K, int BN>
__global__ __launch_bounds__(256, 2) void k_gemm(const float* __restrict__ A, int lda,
                                                 const float* __restrict__ B0,
                                                 const float* __restrict__ B1,
                                                 const float* __restrict__ B2,
                                                 const float* __restrict__ bias,
                                                 float* C, int ldc,
                                                 int do_relu,
                                                 const float* res,
                                                 float* Fout, int fcol,
                                                 const float2* rowscale,
                                                 int nrows) {
    constexpr int BM = 128, KC = 32, NG = BN / 64;   // NG in {1,2}
    __shared__ float As[KC][BM];
    __shared__ float Bs[KC][BN];
    int tid = threadIdx.x;
    int ty = tid >> 4, tx = tid & 15;      // ty 0..15 (8 rows each), tx 0..15 (4 cols/group)
    int r0 = ty * 8;
    int rbase = blockIdx.x * BM;
    const float* B = (blockIdx.y == 0) ? B0 : (blockIdx.y == 1) ? B1 : B2;
    int ccol = blockIdx.y * BN;

    unsigned long long acc[8][NG][2];
#pragma unroll
    for (int i = 0; i < 8; i++)
#pragma unroll
        for (int g = 0; g < NG; g++) { acc[i][g][0] = 0ull; acc[i][g][1] = 0ull; }

    for (int kk = 0; kk < K; kk += KC) {
        // A tile: 128 rows x 32 k = 1024 float4 slots; row fastest -> conflict-free STS
#pragma unroll
        for (int i = 0; i < 4; i++) {
            int slot = tid + i * 256;
            int row = slot & 127, q = slot >> 7;          // q 0..7
            float4 v = make_float4(0.f, 0.f, 0.f, 0.f);
            int gr = rbase + row;
            if (gr < nrows) {
                v = *(const float4*)(A + (size_t)gr * lda + kk + q * 4);
                if (rowscale) {
                    float2 sc = rowscale[gr];
                    float den = ((kk + q * 4) < 64) ? sc.x : sc.y;
                    float inv = __fdividef(1.f, den + 1e-9f);
                    v.x *= inv; v.y *= inv; v.z *= inv; v.w *= inv;
                }
            }
            As[q * 4 + 0][row] = v.x; As[q * 4 + 1][row] = v.y;
            As[q * 4 + 2][row] = v.z; As[q * 4 + 3][row] = v.w;
        }
        // B tile: 32 x BN; consecutive lanes -> contiguous -> conflict-free
#pragma unroll
        for (int i = 0; i < (KC * BN / 4) / 256; i++) {
            int slot = tid + i * 256;
            int kr = slot / (BN / 4), q = slot % (BN / 4);
            *(float4*)&Bs[kr][q * 4] = *(const float4*)(B + (size_t)(kk + kr) * BN + q * 4);
        }
        __syncthreads();
#pragma unroll
        for (int k = 0; k < KC; k++) {
            float4 a0 = *(const float4*)&As[k][r0];
            float4 a1 = *(const float4*)&As[k][r0 + 4];
            unsigned long long aa[8];
            aa[0] = dup2(a0.x); aa[1] = dup2(a0.y); aa[2] = dup2(a0.z); aa[3] = dup2(a0.w);
            aa[4] = dup2(a1.x); aa[5] = dup2(a1.y); aa[6] = dup2(a1.z); aa[7] = dup2(a1.w);
            unsigned long long bb[NG][2];
#pragma unroll
            for (int g = 0; g < NG; g++) {
                ulonglong2 t = *(const ulonglong2*)&Bs[k][g * 64 + tx * 4];
                bb[g][0] = t.x; bb[g][1] = t.y;
            }
#pragma unroll
            for (int i = 0; i < 8; i++)
#pragma unroll
                for (int g = 0; g < NG; g++) {
                    ffma2(acc[i][g][0], aa[i], bb[g][0]);
                    ffma2(acc[i][g][1], aa[i], bb[g][1]);
                }
        }
        __syncthreads();
    }
#pragma unroll
    for (int i = 0; i < 8; i++) {
        int gr = rbase + r0 + i;
        if (gr >= nrows) continue;
#pragma unroll
        for (int g = 0; g < NG; g++)
#pragma unroll
            for (int p = 0; p < 2; p++) {
                float2 v = unpk(acc[i][g][p]);
                int j = g * 64 + tx * 4 + p * 2;
                if (bias) { v.x += bias[j]; v.y += bias[j + 1]; }
                if (do_relu) { v.x = fmaxf(v.x, 0.f); v.y = fmaxf(v.y, 0.f); }
                if (res) { float2 rv = *(const float2*)(res + (size_t)gr * 64 + j); v.x += rv.x; v.y += rv.y; }
                *(float2*)(C + (size_t)gr * ldc + ccol + j) = v;
                if (Fout) *(float2*)(Fout + (size_t)gr * FDIM + fcol + j) = v;
            }
    }
}

// ---------------- FUSED edge pass: logits -> exp -> s-reduction -> message reduction ----------------
// One warp per edge. Math identity used:
//   alpha = exp(e - m)/sum(exp(e - m)) = exp(e)/sum(exp(e))   (max cancels; logits O(1), no overflow)
//   sum_e alpha*np = (sum_e exp(e)*np) / s_d                   (normalization deferred to Wm0 A-load)
__global__ __launch_bounds__(256) void k_edge(int l,
                                              const int* __restrict__ src, const int* __restrict__ dst,
                                              const int* __restrict__ etype, const int* __restrict__ rid,
                                              const float* __restrict__ att_rc, const float* __restrict__ att_rp,
                                              const float* __restrict__ attnv) {
    int lane = threadIdx.x & 31;
    int gw = (blockIdx.x * blockDim.x + threadIdx.x) >> 5;
    int nw = (gridDim.x * blockDim.x) >> 5;
    int c = lane * 4;
    const float* Arc = g_Arc[l]; const float* Arp = g_Arp[l];
    const float* TeP = g_TeP[l]; const float* Trt = g_Tr[l];
    float4 arc0 = *(const float4*)(Arc + c);
    float4 arc1 = *(const float4*)(Arc + 128 + c);
    float4 arp0 = *(const float4*)(Arp + c);
    float4 arp1 = *(const float4*)(Arp + 128 + c);
    float4 arp2 = *(const float4*)(Arp + 256 + c);
    float4 at   = *(const float4*)(attnv + c);
    for (int e = gw; e < EE; e += nw) {
        int s  = __ldg(src + e),   d  = __ldg(dst + e);
        int et = __ldg(etype + e), rr = __ldg(rid + e);
        float2 rc = __ldg((const float2*)att_rc + e);
        const float* rpp = att_rp + (size_t)e * 3;
        float rp0 = __ldg(rpp), rp1 = __ldg(rpp + 1), rp2 = __ldg(rpp + 2);
        float4 te = *(const float4*)(TeP + et * 128 + c);
        float4 tr = *(const float4*)(Trt + rr * 128 + c);
        float4 ni = *(const float4*)(g_NP + (size_t)s * 384 + c);
        float4 nj = *(const float4*)(g_NP + (size_t)d * 384 + 128 + c);
        float fx = ni.x + nj.x + te.x + tr.x + rc.x * arc0.x + rc.y * arc1.x + rp0 * arp0.x + rp1 * arp1.x + rp2 * arp2.x;
        float fy = ni.y + nj.y + te.y + tr.y + rc.x * arc0.y + rc.y * arc1.y + rp0 * arp0.y + rp1 * arp1.y + rp2 * arp2.y;
        float fz = ni.z + nj.z + te.z + tr.z + rc.x * arc0.z + rc.y * arc1.z + rp0 * arp0.z + rp1 * arp1.z + rp2 * arp2.z;
        float fw = ni.w + nj.w + te.w + tr.w + rc.x * arc0.w + rc.y * arc1.w + rp0 * arp0.w + rp1 * arp1.w + rp2 * arp2.w;
        float p;
        p  = (fx > 0.f ? fx : 0.2f * fx) * at.x;
        p += (fy > 0.f ? fy : 0.2f * fy) * at.y;
        p += (fz > 0.f ? fz : 0.2f * fz) * at.z;
        p += (fw > 0.f ? fw : 0.2f * fw) * at.w;
        // reduce within each 16-lane head group
        p += __shfl_xor_sync(0xffffffffu, p, 1);
        p += __shfl_xor_sync(0xffffffffu, p, 2);
        p += __shfl_xor_sync(0xffffffffu, p, 4);
        p += __shfl_xor_sync(0xffffffffu, p, 8);
        float ex = __expf(p);                               // lane's own head
        float exo = __shfl_xor_sync(0xffffffffu, ex, 16);   // other head
        if (lane == 0) red_add_v2(&g_s[(size_t)d * 2], ex, exo);
        float4 np = *(const float4*)(g_NP + (size_t)s * 384 + 256 + c);
        red_add_v4(g_hatt + (size_t)d * 128 + c, ex * np.x, ex * np.y, ex * np.z, ex * np.w);
    }
}

// ---------------- graph max pooling: coalesced row-streaming + mono atomicMax ----------------
__global__ __launch_bounds__(256) void k_pool() {
    int g = blockIdx.y;                     // graph 0..7
    int chunk = blockIdx.x;                 // row chunk 0..24 (250 rows each)
    int t = threadIdx.x;
    int r_lo = chunk * 250, r_hi = r_lo + 250;
    float v0 = -3.4e38f, v1 = -3.4e38f;
    const float* base = g_F + (size_t)g * NPGX * FDIM;
    for (int r = r_lo; r < r_hi; r++) {
        const float* row = base + (size_t)r * FDIM;
        v0 = fmaxf(v0, row[t]);
        if (t < FDIM - 256) v1 = fmaxf(v1, row[256 + t]);
    }
    atomicMax(&g_gmaxU[g * FDIM + t], mono(v0));
    if (t < FDIM - 256) atomicMax(&g_gmaxU[g * FDIM + 256 + t], mono(v1));
}

// ---------------- output assembly: [features | graph_rep] ----------------
__global__ __launch_bounds__(256) void k_out(float2* __restrict__ out) {
    int idx = blockIdx.x * blockDim.x + threadIdx.x;        // float2 index
    const int TOT = NN * (OUTC / 2);                        // 13,300,000
    if (idx >= TOT) return;
    int c2 = idx % (OUTC / 2);
    int rn = idx / (OUTC / 2);
    int g = rn / NPGX;
    float2 v;
    if (c2 < FDIM / 2) {
        v = ((const float2*)g_F)[(size_t)rn * (FDIM / 2) + c2];
    } else {
        int c = (c2 - FDIM / 2) * 2;
        v.x = demono(g_gmaxU[g * FDIM + c]);
        v.y = demono(g_gmaxU[g * FDIM + c + 1]);
    }
    out[idx] = v;
}

// ---------------- host ----------------
extern "C" void kernel_launch(void* const* d_in, const int* in_sizes, int n_in,
                              void* d_out, int out_size) {
    (void)in_sizes; (void)n_in; (void)out_size;
    const float* feat      = (const float*)d_in[0];
    const float* att_rc    = (const float*)d_in[1];
    const float* att_rp    = (const float*)d_in[2];
    const float* etype_emb = (const float*)d_in[3];
    const float* rid_emb   = (const float*)d_in[4];
    const float* rc_W      = (const float*)d_in[5];
    const float* rc_b      = (const float*)d_in[6];
    const float* rp_W      = (const float*)d_in[7];
    const float* rp_b      = (const float*)d_in[8];
    const float* fe_W0     = (const float*)d_in[9];
    const float* fe_b0     = (const float*)d_in[10];
    const float* fe_W1     = (const float*)d_in[11];
    const float* fe_b1     = (const float*)d_in[12];
    const float* W_ni      = (const float*)d_in[13];
    const float* W_nj      = (const float*)d_in[14];
    const float* W_fij     = (const float*)d_in[15];
    const float* W_node    = (const float*)d_in[16];
    const float* attn      = (const float*)d_in[17];
    const float* egat_bias = (const float*)d_in[18];
    const float* Wm0       = (const float*)d_in[19];
    const float* bm0       = (const float*)d_in[20];
    const float* Wm1       = (const float*)d_in[21];
    const float* bm1       = (const float*)d_in[22];
    const int*   src       = (const int*)d_in[23];
    const int*   dst       = (const int*)d_in[24];
    const int*   etype     = (const int*)d_in[25];
    const int*   rid       = (const int*)d_in[26];

    float *pH, *pT, *pNP, *phatt, *pF, *ps;
    unsigned *pgmax;
    cudaGetSymbolAddress((void**)&pH,    g_H);
    cudaGetSymbolAddress((void**)&pT,    g_T);
    cudaGetSymbolAddress((void**)&pNP,   g_NP);
    cudaGetSymbolAddress((void**)&phatt, g_hatt);
    cudaGetSymbolAddress((void**)&pF,    g_F);
    cudaGetSymbolAddress((void**)&ps,    g_s);
    cudaGetSymbolAddress((void**)&pgmax, g_gmaxU);

    const int GB = (NN + 127) / 128;   // 391 blocks of 128 rows

    k_feat1<<<GB, 128>>>(feat, fe_W0, fe_b0);
    k_tables<<<3, 256>>>(etype_emb, rid_emb, rc_W, rc_b, rp_W, rp_b, W_fij, egat_bias);
    // h0 = T@W1 + b1 ; also writes F[:,10:74]
    k_gemm<64, 64><<<dim3(GB, 1), 256>>>(pT, 128, fe_W1, nullptr, nullptr, fe_b1,
                                         pH, 64, 0, nullptr, pF, 10, nullptr, NN);

    for (int l = 0; l < 3; l++) {
        cudaMemsetAsync(phatt, 0, (size_t)NN * 128 * sizeof(float));
        cudaMemsetAsync(ps,    0, (size_t)NN * 2 * sizeof(float));
        // fused: NP[:,0:384] = H @ [W_ni | W_nj | W_node]
        k_gemm<64, 128><<<dim3(GB, 3), 256>>>(pH, 64,
                                              W_ni + (size_t)l * 64 * 128,
                                              W_nj + (size_t)l * 64 * 128,
                                              W_node + (size_t)l * 64 * 128,
                                              nullptr, pNP, 384, 0, nullptr, nullptr, 0, nullptr, NN);
        // single fused edge pass: logits + exp + s + unnormalized messages
        k_edge<<<1184, 256>>>(l, src, dst, etype, rid, att_rc, att_rp, attn + (size_t)l * 128);
        // T = relu( (hatt/s) @ Wm0 + bm0 )  -- normalization via rowscale
        k_gemm<128, 128><<<dim3(GB, 1), 256>>>(phatt, 128,
                                               Wm0 + (size_t)l * 128 * 128, nullptr, nullptr,
                                               bm0 + (size_t)l * 128,
                                               pT, 128, 1, nullptr, nullptr, 0, (const float2*)ps, NN);
        // H = T @ Wm1 + bm1 + H ; also writes F slice
        k_gemm<128, 64><<<dim3(GB, 1), 256>>>(pT, 128,
                                              Wm1 + (size_t)l * 128 * 64, nullptr, nullptr,
                                              bm1 + (size_t)l * 64,
                                              pH, 64, 0, pH, pF, 10 + 64 * (l + 1), nullptr, NN);
    }
    cudaMemsetAsync(pgmax, 0, (size_t)NB * FDIM * sizeof(unsigned));
    k_pool<<<dim3(25, NB), 256>>>();
    k_out<<<(NN * (OUTC / 2) + 255) / 256, 256>>>((float2*)d_out);
}

// round 15
// speedup vs baseline: 1.9365x; 1.0323x over previous
#include <cuda_runtime.h>

#define NN 50000
#define EE 500000
#define NB 8
#define NPGX 6250
#define FDIM 266   // 10 + 4*64
#define OUTC 532
#define CHUNK 25   // edges per warp in sorted-edge pass (EE/CHUNK = 20000 warps)

// ---------------- scratch (device globals: no runtime allocation allowed) ----------------
__device__ float    g_F[(size_t)NN * FDIM];   // concat features
__device__ float    g_H[(size_t)NN * 64];     // current h
__device__ float    g_T[(size_t)NN * 128];    // MLP hidden / feat-MLP hidden
__device__ float    g_NP[(size_t)NN * 384];   // [ni | nj | nproj]
__device__ float    g_hatt[(size_t)NN * 128]; // UNNORMALIZED sum of ex*nproj[src]
__device__ float    g_s[NN * 2];              // softmax denom (sum of ex per head)
__device__ unsigned g_gmaxU[NB * FDIM];       // mono-encoded graph max
__device__ float    g_TeP[3][7 * 128];        // etype table (+ (rc_b+rp_b)@Wf + egat_bias)
__device__ float    g_Tr[3][31 * 128];
__device__ float    g_Arc[3][2 * 128];
__device__ float    g_Arp[3][3 * 128];
// edge sort scratch
__device__ int      g_cnt[NN];                // per-dst edge count / histogram
__device__ int      g_cur[NN];                // scatter cursors
__device__ float4   g_E1[EE];                 // sorted: {rc.x, rc.y, rp0, rp1}
__device__ uint4    g_E2[EE];                 // sorted: {rp2(bits), src, etype|rid<<8, dst}

// ---------------- helpers ----------------
__device__ __forceinline__ void ffma2(unsigned long long& d, unsigned long long a, unsigned long long b) {
    asm("fma.rn.f32x2 %0, %1, %2, %0;" : "+l"(d) : "l"(a), "l"(b));
}
__device__ __forceinline__ unsigned long long dup2(float x) {
    unsigned long long r; asm("mov.b64 %0, {%1, %1};" : "=l"(r) : "f"(x)); return r;
}
__device__ __forceinline__ float2 unpk(unsigned long long v) {
    float2 r; asm("mov.b64 {%0, %1}, %2;" : "=f"(r.x), "=f"(r.y) : "l"(v)); return r;
}
__device__ __forceinline__ void red_add_v4(float* p, float a, float b, float c, float d) {
    asm volatile("red.global.add.v4.f32 [%0], {%1,%2,%3,%4};"
                 :: "l"(p), "f"(a), "f"(b), "f"(c), "f"(d) : "memory");
}
__device__ __forceinline__ void red_add_v2(float* p, float a, float b) {
    asm volatile("red.global.add.v2.f32 [%0], {%1,%2};"
                 :: "l"(p), "f"(a), "f"(b) : "memory");
}
__device__ __forceinline__ unsigned mono(float f) {
    unsigned u = __float_as_uint(f);
    return u ^ (((unsigned)((int)u >> 31)) | 0x80000000u);
}
__device__ __forceinline__ float demono(unsigned u) {
    unsigned v = (u & 0x80000000u) ? (u ^ 0x80000000u) : ~u;
    return __uint_as_float(v);
}

// ---------------- edge sort: histogram -> scan -> scatter (once per launch) ----------------
__global__ __launch_bounds__(256) void k_hist(const int* __restrict__ dst) {
    int e = blockIdx.x * blockDim.x + threadIdx.x;
    if (e < EE) atomicAdd(&g_cnt[__ldg(dst + e)], 1);
}

__global__ __launch_bounds__(1024) void k_scan() {   // single block
    __shared__ int ssum[1024];
    int t = threadIdx.x;
    const int PER = (NN + 1023) / 1024;              // 49
    int base = t * PER, end = min(base + PER, NN);
    int s = 0;
    for (int i = base; i < end; i++) s += g_cnt[i];
    ssum[t] = s;
    __syncthreads();
    // inclusive Hillis-Steele scan
    for (int off = 1; off < 1024; off <<= 1) {
        int v = (t >= off) ? ssum[t - off] : 0;
        __syncthreads();
        ssum[t] += v;
        __syncthreads();
    }
    int run = ssum[t] - s;                           // exclusive prefix for this chunk
    for (int i = base; i < end; i++) {
        int c = g_cnt[i];
        g_cur[i] = run;
        run += c;
    }
}

__global__ __launch_bounds__(256) void k_scatter(const int* __restrict__ src, const int* __restrict__ dst,
                                                 const int* __restrict__ etype, const int* __restrict__ rid,
                                                 const float* __restrict__ att_rc, const float* __restrict__ att_rp) {
    int e = blockIdx.x * blockDim.x + threadIdx.x;
    if (e >= EE) return;
    int d = __ldg(dst + e);
    int pos = atomicAdd(&g_cur[d], 1);
    float2 rc = __ldg((const float2*)att_rc + e);
    const float* rpp = att_rp + (size_t)e * 3;
    float rp0 = __ldg(rpp), rp1 = __ldg(rpp + 1), rp2 = __ldg(rpp + 2);
    g_E1[pos] = make_float4(rc.x, rc.y, rp0, rp1);
    uint4 r;
    r.x = __float_as_uint(rp2);
    r.y = (unsigned)__ldg(src + e);
    r.z = (unsigned)(__ldg(etype + e) | (__ldg(rid + e) << 8));
    r.w = (unsigned)d;
    g_E2[pos] = r;
}

// ---------------- feature MLP stage 1: T = relu(feat@W0+b0) ; copies feat -> F[:,0:10] ----------------
__global__ __launch_bounds__(128) void k_feat1(const float* __restrict__ feat,
                                               const float* __restrict__ W0, const float* __restrict__ b0) {
    __shared__ float sW0[640], sb0[64];
    int tid = threadIdx.x;
    for (int i = tid; i < 640; i += 128) sW0[i] = W0[i];
    if (tid < 64) sb0[tid] = b0[tid];
    __syncthreads();
    int row = blockIdx.x * 128 + tid;
    if (row >= NN) return;
    float x[10];
#pragma unroll
    for (int k = 0; k < 10; k++) x[k] = feat[(size_t)row * 10 + k];
#pragma unroll
    for (int k = 0; k < 10; k++) g_F[(size_t)row * FDIM + k] = x[k];
    for (int j = 0; j < 64; j++) {
        float a = sb0[j];
#pragma unroll
        for (int k = 0; k < 10; k++) a += x[k] * sW0[k * 64 + j];
        g_T[(size_t)row * 128 + j] = fmaxf(a, 0.f);
    }
}

// ---------------- per-layer edge tables: fold W_fij into tiny lookup tables ----------------
__global__ __launch_bounds__(256) void k_tables(const float* __restrict__ etype_emb, const float* __restrict__ rid_emb,
                                                const float* __restrict__ rc_W, const float* __restrict__ rc_b,
                                                const float* __restrict__ rp_W, const float* __restrict__ rp_b,
                                                const float* __restrict__ W_fij, const float* __restrict__ egat_bias) {
    int l = blockIdx.x;
    const float* Wf = W_fij + (size_t)l * 64 * 128;
    __shared__ float rows[43][64];
    __shared__ float cb[64];
    int tid = threadIdx.x;
    if (tid < 64) cb[tid] = rc_b[tid] + rp_b[tid];
    __syncthreads();
    for (int i = tid; i < 7 * 64;  i += 256) rows[i / 64][i % 64]      = etype_emb[i] + cb[i % 64];
    for (int i = tid; i < 31 * 64; i += 256) rows[7 + i / 64][i % 64]  = rid_emb[i];
    for (int i = tid; i < 2 * 64;  i += 256) rows[38 + i / 64][i % 64] = rc_W[i];
    for (int i = tid; i < 3 * 64;  i += 256) rows[40 + i / 64][i % 64] = rp_W[i];
    __syncthreads();
    for (int idx = tid; idx < 43 * 128; idx += 256) {
        int r = idx >> 7, o = idx & 127;
        float a = 0.f;
#pragma unroll
        for (int k = 0; k < 64; k++) a += rows[r][k] * Wf[k * 128 + o];
        if (r < 7)       g_TeP[l][r * 128 + o] = a + egat_bias[l * 128 + o];
        else if (r < 38) g_Tr[l][(r - 7) * 128 + o] = a;
        else if (r < 40) g_Arc[l][(r - 38) * 128 + o] = a;
        else             g_Arp[l][(r - 40) * 128 + o] = a;
    }
}

// ---------------- f32x2 GEMM: BM=128, 8x8 micro-tile (8x4 for BN=64), occ 2 ----------------
template<int K, int BN>
__global__ __launch_bounds__(256, 2) void k_gemm(const float* __restrict__ A, int lda,
                                                 const float* __restrict__ B0,
                                                 const float* __restrict__ B1,
                                                 const float* __restrict__ B2,
                                                 const float* __restrict__ bias,
                                                 float* C, int ldc,
                                                 int do_relu,
                                                 const float* res,
                                                 float* Fout, int fcol,
                                                 const float2* rowscale,
                                                 int nrows) {
    constexpr int BM = 128, KC = 32, NG = BN / 64;   // NG in {1,2}
    __shared__ float As[KC][BM];
    __shared__ float Bs[KC][BN];
    int tid = threadIdx.x;
    int ty = tid >> 4, tx = tid & 15;
    int r0 = ty * 8;
    int rbase = blockIdx.x * BM;
    const float* B = (blockIdx.y == 0) ? B0 : (blockIdx.y == 1) ? B1 : B2;
    int ccol = blockIdx.y * BN;

    unsigned long long acc[8][NG][2];
#pragma unroll
    for (int i = 0; i < 8; i++)
#pragma unroll
        for (int g = 0; g < NG; g++) { acc[i][g][0] = 0ull; acc[i][g][1] = 0ull; }

    for (int kk = 0; kk < K; kk += KC) {
#pragma unroll
        for (int i = 0; i < 4; i++) {
            int slot = tid + i * 256;
            int row = slot & 127, q = slot >> 7;
            float4 v = make_float4(0.f, 0.f, 0.f, 0.f);
            int gr = rbase + row;
            if (gr < nrows) {
                v = *(const float4*)(A + (size_t)gr * lda + kk + q * 4);
                if (rowscale) {
                    float2 sc = rowscale[gr];
                    float den = ((kk + q * 4) < 64) ? sc.x : sc.y;
                    float inv = __fdividef(1.f, den + 1e-9f);
                    v.x *= inv; v.y *= inv; v.z *= inv; v.w *= inv;
                }
            }
            As[q * 4 + 0][row] = v.x; As[q * 4 + 1][row] = v.y;
            As[q * 4 + 2][row] = v.z; As[q * 4 + 3][row] = v.w;
        }
#pragma unroll
        for (int i = 0; i < (KC * BN / 4) / 256; i++) {
            int slot = tid + i * 256;
            int kr = slot / (BN / 4), q = slot % (BN / 4);
            *(float4*)&Bs[kr][q * 4] = *(const float4*)(B + (size_t)(kk + kr) * BN + q * 4);
        }
        __syncthreads();
#pragma unroll
        for (int k = 0; k < KC; k++) {
            float4 a0 = *(const float4*)&As[k][r0];
            float4 a1 = *(const float4*)&As[k][r0 + 4];
            unsigned long long aa[8];
            aa[0] = dup2(a0.x); aa[1] = dup2(a0.y); aa[2] = dup2(a0.z); aa[3] = dup2(a0.w);
            aa[4] = dup2(a1.x); aa[5] = dup2(a1.y); aa[6] = dup2(a1.z); aa[7] = dup2(a1.w);
            unsigned long long bb[NG][2];
#pragma unroll
            for (int g = 0; g < NG; g++) {
                ulonglong2 t = *(const ulonglong2*)&Bs[k][g * 64 + tx * 4];
                bb[g][0] = t.x; bb[g][1] = t.y;
            }
#pragma unroll
            for (int i = 0; i < 8; i++)
#pragma unroll
                for (int g = 0; g < NG; g++) {
                    ffma2(acc[i][g][0], aa[i], bb[g][0]);
                    ffma2(acc[i][g][1], aa[i], bb[g][1]);
                }
        }
        __syncthreads();
    }
#pragma unroll
    for (int i = 0; i < 8; i++) {
        int gr = rbase + r0 + i;
        if (gr >= nrows) continue;
#pragma unroll
        for (int g = 0; g < NG; g++)
#pragma unroll
            for (int p = 0; p < 2; p++) {
                float2 v = unpk(acc[i][g][p]);
                int j = g * 64 + tx * 4 + p * 2;
                if (bias) { v.x += bias[j]; v.y += bias[j + 1]; }
                if (do_relu) { v.x = fmaxf(v.x, 0.f); v.y = fmaxf(v.y, 0.f); }
                if (res) { float2 rv = *(const float2*)(res + (size_t)gr * 64 + j); v.x += rv.x; v.y += rv.y; }
                *(float2*)(C + (size_t)gr * ldc + ccol + j) = v;
                if (Fout) *(float2*)(Fout + (size_t)gr * FDIM + fcol + j) = v;
            }
    }
}

// ---------------- FUSED edge pass over dst-sorted edges ----------------
// One warp walks CHUNK consecutive sorted edges; nj[dst] loaded once per run;
// hatt/s accumulated in registers per run, flushed via red.add (boundary-safe).
__global__ __launch_bounds__(256) void k_edge(int l, const float* __restrict__ attnv) {
    __shared__ float sTe[7 * 128];
    __shared__ float sTr[31 * 128];
    int tid = threadIdx.x;
    for (int i = tid; i < 7 * 128;  i += 256) sTe[i] = g_TeP[l][i];
    for (int i = tid; i < 31 * 128; i += 256) sTr[i] = g_Tr[l][i];
    __syncthreads();

    int lane = tid & 31;
    int gw = (blockIdx.x * blockDim.x + tid) >> 5;
    int c = lane * 4;
    const float* Arc = g_Arc[l]; const float* Arp = g_Arp[l];
    float4 arc0 = *(const float4*)(Arc + c);
    float4 arc1 = *(const float4*)(Arc + 128 + c);
    float4 arp0 = *(const float4*)(Arp + c);
    float4 arp1 = *(const float4*)(Arp + 128 + c);
    float4 arp2 = *(const float4*)(Arp + 256 + c);
    float4 at   = *(const float4*)(attnv + c);

    int e0 = gw * CHUNK;
    if (e0 >= EE) return;
    int e1 = min(e0 + CHUNK, EE);

    int cur = -1;
    float4 racc = make_float4(0.f, 0.f, 0.f, 0.f);
    float rs = 0.f;
    float4 nj = make_float4(0.f, 0.f, 0.f, 0.f);

    for (int e = e0; e < e1; e++) {
        float4 E1 = __ldg(g_E1 + e);
        uint4  E2 = __ldg(g_E2 + e);
        float rp2 = __uint_as_float(E2.x);
        int s = (int)E2.y;
        int et = (int)(E2.z & 255u), rr = (int)(E2.z >> 8);
        int dd = (int)E2.w;
        if (dd != cur) {
            if (cur >= 0) {
                red_add_v4(g_hatt + (size_t)cur * 128 + c, racc.x, racc.y, racc.z, racc.w);
                float rso = __shfl_sync(0xffffffffu, rs, 16);
                if (lane == 0) red_add_v2(&g_s[(size_t)cur * 2], rs, rso);
            }
            cur = dd;
            racc = make_float4(0.f, 0.f, 0.f, 0.f);
            rs = 0.f;
            nj = *(const float4*)(g_NP + (size_t)dd * 384 + 128 + c);
        }
        float4 te = *(const float4*)(sTe + et * 128 + c);
        float4 tr = *(const float4*)(sTr + rr * 128 + c);
        float4 ni = *(const float4*)(g_NP + (size_t)s * 384 + c);
        float fx = ni.x + nj.x + te.x + tr.x + E1.x * arc0.x + E1.y * arc1.x + E1.z * arp0.x + E1.w * arp1.x + rp2 * arp2.x;
        float fy = ni.y + nj.y + te.y + tr.y + E1.x * arc0.y + E1.y * arc1.y + E1.z * arp0.y + E1.w * arp1.y + rp2 * arp2.y;
        float fz = ni.z + nj.z + te.z + tr.z + E1.x * arc0.z + E1.y * arc1.z + E1.z * arp0.z + E1.w * arp1.z + rp2 * arp2.z;
        float fw = ni.w + nj.w + te.w + tr.w + E1.x * arc0.w + E1.y * arc1.w + E1.z * arp0.w + E1.w * arp1.w + rp2 * arp2.w;
        float p;
        p  = (fx > 0.f ? fx : 0.2f * fx) * at.x;
        p += (fy > 0.f ? fy : 0.2f * fy) * at.y;
        p += (fz > 0.f ? fz : 0.2f * fz) * at.z;
        p += (fw > 0.f ? fw : 0.2f * fw) * at.w;
        p += __shfl_xor_sync(0xffffffffu, p, 1);
        p += __shfl_xor_sync(0xffffffffu, p, 2);
        p += __shfl_xor_sync(0xffffffffu, p, 4);
        p += __shfl_xor_sync(0xffffffffu, p, 8);
        float ex = __expf(p);                           // per-lane head value
        float4 np = *(const float4*)(g_NP + (size_t)s * 384 + 256 + c);
        racc.x += ex * np.x; racc.y += ex * np.y;
        racc.z += ex * np.z; racc.w += ex * np.w;
        rs += ex;
    }
    if (cur >= 0) {
        red_add_v4(g_hatt + (size_t)cur * 128 + c, racc.x, racc.y, racc.z, racc.w);
        float rso = __shfl_sync(0xffffffffu, rs, 16);
        if (lane == 0) red_add_v2(&g_s[(size_t)cur * 2], rs, rso);
    }
}

// ---------------- graph max pooling: coalesced row-streaming + mono atomicMax ----------------
__global__ __launch_bounds__(256) void k_pool() {
    int g = blockIdx.y;
    int chunk = blockIdx.x;
    int t = threadIdx.x;
    int r_lo = chunk * 250, r_hi = r_lo + 250;
    float v0 = -3.4e38f, v1 = -3.4e38f;
    const float* base = g_F + (size_t)g * NPGX * FDIM;
    for (int r = r_lo; r < r_hi; r++) {
        const float* row = base + (size_t)r * FDIM;
        v0 = fmaxf(v0, row[t]);
        if (t < FDIM - 256) v1 = fmaxf(v1, row[256 + t]);
    }
    atomicMax(&g_gmaxU[g * FDIM + t], mono(v0));
    if (t < FDIM - 256) atomicMax(&g_gmaxU[g * FDIM + 256 + t], mono(v1));
}

// ---------------- output assembly: [features | graph_rep] ----------------
__global__ __launch_bounds__(256) void k_out(float2* __restrict__ out) {
    int idx = blockIdx.x * blockDim.x + threadIdx.x;
    const int TOT = NN * (OUTC / 2);
    if (idx >= TOT) return;
    int c2 = idx % (OUTC / 2);
    int rn = idx / (OUTC / 2);
    int g = rn / NPGX;
    float2 v;
    if (c2 < FDIM / 2) {
        v = ((const float2*)g_F)[(size_t)rn * (FDIM / 2) + c2];
    } else {
        int c = (c2 - FDIM / 2) * 2;
        v.x = demono(g_gmaxU[g * FDIM + c]);
        v.y = demono(g_gmaxU[g * FDIM + c + 1]);
    }
    out[idx] = v;
}

// ---------------- host ----------------
extern "C" void kernel_launch(void* const* d_in, const int* in_sizes, int n_in,
                              void* d_out, int out_size) {
    (void)in_sizes; (void)n_in; (void)out_size;
    const float* feat      = (const float*)d_in[0];
    const float* att_rc    = (const float*)d_in[1];
    const float* att_rp    = (const float*)d_in[2];
    const float* etype_emb = (const float*)d_in[3];
    const float* rid_emb   = (const float*)d_in[4];
    const float* rc_W      = (const float*)d_in[5];
    const float* rc_b      = (const float*)d_in[6];
    const float* rp_W      = (const float*)d_in[7];
    const float* rp_b      = (const float*)d_in[8];
    const float* fe_W0     = (const float*)d_in[9];
    const float* fe_b0     = (const float*)d_in[10];
    const float* fe_W1     = (const float*)d_in[11];
    const float* fe_b1     = (const float*)d_in[12];
    const float* W_ni      = (const float*)d_in[13];
    const float* W_nj      = (const float*)d_in[14];
    const float* W_fij     = (const float*)d_in[15];
    const float* W_node    = (const float*)d_in[16];
    const float* attn      = (const float*)d_in[17];
    const float* egat_bias = (const float*)d_in[18];
    const float* Wm0       = (const float*)d_in[19];
    const float* bm0       = (const float*)d_in[20];
    const float* Wm1       = (const float*)d_in[21];
    const float* bm1       = (const float*)d_in[22];
    const int*   src       = (const int*)d_in[23];
    const int*   dst       = (const int*)d_in[24];
    const int*   etype     = (const int*)d_in[25];
    const int*   rid       = (const int*)d_in[26];

    float *pH, *pT, *pNP, *phatt, *pF, *ps;
    unsigned *pgmax;
    int *pcnt;
    cudaGetSymbolAddress((void**)&pH,    g_H);
    cudaGetSymbolAddress((void**)&pT,    g_T);
    cudaGetSymbolAddress((void**)&pNP,   g_NP);
    cudaGetSymbolAddress((void**)&phatt, g_hatt);
    cudaGetSymbolAddress((void**)&pF,    g_F);
    cudaGetSymbolAddress((void**)&ps,    g_s);
    cudaGetSymbolAddress((void**)&pgmax, g_gmaxU);
    cudaGetSymbolAddress((void**)&pcnt,  g_cnt);

    const int GB = (NN + 127) / 128;   // 391 blocks of 128 rows
    const int EB = (EE + 255) / 256;

    // ---- one-time edge sort by dst ----
    cudaMemsetAsync(pcnt, 0, NN * sizeof(int));
    k_hist<<<EB, 256>>>(dst);
    k_scan<<<1, 1024>>>();
    k_scatter<<<EB, 256>>>(src, dst, etype, rid, att_rc, att_rp);

    k_feat1<<<GB, 128>>>(feat, fe_W0, fe_b0);
    k_tables<<<3, 256>>>(etype_emb, rid_emb, rc_W, rc_b, rp_W, rp_b, W_fij, egat_bias);
    k_gemm<64, 64><<<dim3(GB, 1), 256>>>(pT, 128, fe_W1, nullptr, nullptr, fe_b1,
                                         pH, 64, 0, nullptr, pF, 10, nullptr, NN);

    for (int l = 0; l < 3; l++) {
        cudaMemsetAsync(phatt, 0, (size_t)NN * 128 * sizeof(float));
        cudaMemsetAsync(ps,    0, (size_t)NN * 2 * sizeof(float));
        k_gemm<64, 128><<<dim3(GB, 3), 256>>>(pH, 64,
                                              W_ni + (size_t)l * 64 * 128,
                                              W_nj + (size_t)l * 64 * 128,
                                              W_node + (size_t)l * 64 * 128,
                                              nullptr, pNP, 384, 0, nullptr, nullptr, 0, nullptr, NN);
        k_edge<<<(EE / CHUNK + 7) / 8, 256>>>(l, attn + (size_t)l * 128);
        k_gemm<128, 128><<<dim3(GB, 1), 256>>>(phatt, 128,
                                               Wm0 + (size_t)l * 128 * 128, nullptr, nullptr,
                                               bm0 + (size_t)l * 128,
                                               pT, 128, 1, nullptr, nullptr, 0, (const float2*)ps, NN);
        k_gemm<128, 64><<<dim3(GB, 1), 256>>>(pT, 128,
                                              Wm1 + (size_t)l * 128 * 64, nullptr, nullptr,
                                              bm1 + (size_t)l * 64,
                                              pH, 64, 0, pH, pF, 10 + 64 * (l + 1), nullptr, NN);
    }
    cudaMemsetAsync(pgmax, 0, (size_t)NB * FDIM * sizeof(unsigned));
    k_pool<<<dim3(25, NB), 256>>>();
    k_out<<<(NN * (OUTC / 2) + 255) / 256, 256>>>((float2*)d_out);
}

// round 17
// speedup vs baseline: 2.0874x; 1.0779x over previous
#include <cuda_runtime.h>
#include <cuda_fp16.h>

#define NN 50000
#define EE 500000
#define NB 8
#define NPGX 6250
#define FDIM 266   // 10 + 4*64
#define OUTC 532
#define CHUNK 25   // edges per warp in sorted-edge pass

// ---------------- scratch ----------------
__device__ float    g_H[(size_t)NN * 64];     // current h
__device__ float    g_T[(size_t)NN * 128];    // MLP hidden
__device__ __half   g_NIJ[(size_t)NN * 256];  // fp16 [ni | nj]  (logit path only)
__device__ float    g_NPp[(size_t)NN * 128];  // fp32 nproj      (message path)
__device__ float    g_hatt[(size_t)NN * 128]; // UNNORMALIZED sum of ex*nproj[src]
__device__ float    g_s[NN * 2];              // softmax denom
__device__ unsigned g_gmaxU[NB * FDIM];       // mono-encoded graph max
__device__ float    g_TeP[3][7 * 128];
__device__ float    g_Tr[3][31 * 128];
__device__ float    g_Arc[3][2 * 128];
__device__ float    g_Arp[3][3 * 128];
// edge sort scratch
__device__ int      g_cnt[NN];
__device__ int      g_cur[NN];
__device__ float4   g_E1[EE];                 // sorted: {rc.x, rc.y, rp0, rp1}
__device__ uint4    g_E2[EE];                 // sorted: {rp2(bits), src, etype|rid<<8, dst}

// ---------------- helpers ----------------
__device__ __forceinline__ void ffma2(unsigned long long& d, unsigned long long a, unsigned long long b) {
    asm("fma.rn.f32x2 %0, %1, %2, %0;" : "+l"(d) : "l"(a), "l"(b));
}
__device__ __forceinline__ unsigned long long dup2(float x) {
    unsigned long long r; asm("mov.b64 %0, {%1, %1};" : "=l"(r) : "f"(x)); return r;
}
__device__ __forceinline__ float2 unpk(unsigned long long v) {
    float2 r; asm("mov.b64 {%0, %1}, %2;" : "=f"(r.x), "=f"(r.y) : "l"(v)); return r;
}
__device__ __forceinline__ void red_add_v4(float* p, float a, float b, float c, float d) {
    asm volatile("red.global.add.v4.f32 [%0], {%1,%2,%3,%4};"
                 :: "l"(p), "f"(a), "f"(b), "f"(c), "f"(d) : "memory");
}
__device__ __forceinline__ void red_add_v2(float* p, float a, float b) {
    asm volatile("red.global.add.v2.f32 [%0], {%1,%2};"
                 :: "l"(p), "f"(a), "f"(b) : "memory");
}
__device__ __forceinline__ unsigned mono(float f) {
    unsigned u = __float_as_uint(f);
    return u ^ (((unsigned)((int)u >> 31)) | 0x80000000u);
}
__device__ __forceinline__ float demono(unsigned u) {
    unsigned v = (u & 0x80000000u) ? (u ^ 0x80000000u) : ~u;
    return __uint_as_float(v);
}
__device__ __forceinline__ float4 nij4(uint2 u) {
    __half2 h0 = *(__half2*)&u.x, h1 = *(__half2*)&u.y;
    float2 f0 = __half22float2(h0), f1 = __half22float2(h1);
    return make_float4(f0.x, f0.y, f1.x, f1.y);
}

// ---------------- edge sort: histogram -> scan -> scatter ----------------
__global__ __launch_bounds__(256) void k_hist(const int* __restrict__ dst) {
    int e = blockIdx.x * blockDim.x + threadIdx.x;
    if (e < EE) atomicAdd(&g_cnt[__ldg(dst + e)], 1);
}

__global__ __launch_bounds__(1024) void k_scan() {   // single block
    __shared__ int ssum[1024];
    int t = threadIdx.x;
    const int PER = (NN + 1023) / 1024;
    int base = t * PER, end = min(base + PER, NN);
    int s = 0;
    for (int i = base; i < end; i++) s += g_cnt[i];
    ssum[t] = s;
    __syncthreads();
    for (int off = 1; off < 1024; off <<= 1) {
        int v = (t >= off) ? ssum[t - off] : 0;
        __syncthreads();
        ssum[t] += v;
        __syncthreads();
    }
    int run = ssum[t] - s;
    for (int i = base; i < end; i++) {
        int c = g_cnt[i];
        g_cur[i] = run;
        run += c;
    }
}

__global__ __launch_bounds__(256) void k_scatter(const int* __restrict__ src, const int* __restrict__ dst,
                                                 const int* __restrict__ etype, const int* __restrict__ rid,
                                                 const float* __restrict__ att_rc, const float* __restrict__ att_rp) {
    int e = blockIdx.x * blockDim.x + threadIdx.x;
    if (e >= EE) return;
    int d = __ldg(dst + e);
    int pos = atomicAdd(&g_cur[d], 1);
    float2 rc = __ldg((const float2*)att_rc + e);
    const float* rpp = att_rp + (size_t)e * 3;
    float rp0 = __ldg(rpp), rp1 = __ldg(rpp + 1), rp2 = __ldg(rpp + 2);
    g_E1[pos] = make_float4(rc.x, rc.y, rp0, rp1);
    uint4 r;
    r.x = __float_as_uint(rp2);
    r.y = (unsigned)__ldg(src + e);
    r.z = (unsigned)(__ldg(etype + e) | (__ldg(rid + e) << 8));
    r.w = (unsigned)d;
    g_E2[pos] = r;
}

// ---------------- feature MLP stage 1 (smem-staged): T = relu(feat@W0+b0); feat -> out[:,0:10] ----------------
__global__ __launch_bounds__(128) void k_feat1(const float* __restrict__ feat,
                                               const float* __restrict__ W0, const float* __restrict__ b0,
                                               float* __restrict__ out) {
    __shared__ float sW0[640], sb0[64];
    __shared__ float sx[128][11];
    int tid = threadIdx.x;
    for (int i = tid; i < 640; i += 128) sW0[i] = W0[i];
    if (tid < 64) sb0[tid] = b0[tid];
    int rbase = blockIdx.x * 128;
    int nrow = min(128, NN - rbase);
    for (int i = tid; i < nrow * 10; i += 128)
        sx[i / 10][i % 10] = feat[(size_t)rbase * 10 + i];
    __syncthreads();
    if (tid >= nrow) return;
    int row = rbase + tid;
    float x[10];
#pragma unroll
    for (int k = 0; k < 10; k++) x[k] = sx[tid][k];
#pragma unroll
    for (int k = 0; k < 10; k++) out[(size_t)row * OUTC + k] = x[k];
    for (int j = 0; j < 64; j++) {
        float a = sb0[j];
#pragma unroll
        for (int k = 0; k < 10; k++) a += x[k] * sW0[k * 64 + j];
        g_T[(size_t)row * 128 + j] = fmaxf(a, 0.f);
    }
}

// ---------------- per-layer edge tables ----------------
__global__ __launch_bounds__(256) void k_tables(const float* __restrict__ etype_emb, const float* __restrict__ rid_emb,
                                                const float* __restrict__ rc_W, const float* __restrict__ rc_b,
                                                const float* __restrict__ rp_W, const float* __restrict__ rp_b,
                                                const float* __restrict__ W_fij, const float* __restrict__ egat_bias) {
    int l = blockIdx.x;
    const float* Wf = W_fij + (size_t)l * 64 * 128;
    __shared__ float rows[43][64];
    __shared__ float cb[64];
    int tid = threadIdx.x;
    if (tid < 64) cb[tid] = rc_b[tid] + rp_b[tid];
    __syncthreads();
    for (int i = tid; i < 7 * 64;  i += 256) rows[i / 64][i % 64]      = etype_emb[i] + cb[i % 64];
    for (int i = tid; i < 31 * 64; i += 256) rows[7 + i / 64][i % 64]  = rid_emb[i];
    for (int i = tid; i < 2 * 64;  i += 256) rows[38 + i / 64][i % 64] = rc_W[i];
    for (int i = tid; i < 3 * 64;  i += 256) rows[40 + i / 64][i % 64] = rp_W[i];
    __syncthreads();
    for (int idx = tid; idx < 43 * 128; idx += 256) {
        int r = idx >> 7, o = idx & 127;
        float a = 0.f;
#pragma unroll
        for (int k = 0; k < 64; k++) a += rows[r][k] * Wf[k * 128 + o];
        if (r < 7)       g_TeP[l][r * 128 + o] = a + egat_bias[l * 128 + o];
        else if (r < 38) g_Tr[l][(r - 7) * 128 + o] = a;
        else if (r < 40) g_Arc[l][(r - 38) * 128 + o] = a;
        else             g_Arp[l][(r - 40) * 128 + o] = a;
    }
}

// ---------------- f32x2 GEMM: BM=128, 8x8 micro-tile, occ 2 ----------------
// npmode: y<2 -> fp16 to g_NIJ (col y*128); y==2 -> fp32 to C (col 0).
template<int K, int BN>
__global__ __launch_bounds__(256, 2) void k_gemm(const float* __restrict__ A, int lda,
                                                 const float* __restrict__ B0,
                                                 const float* __restrict__ B1,
                                                 const float* __restrict__ B2,
                                                 const float* __restrict__ bias,
                                                 float* C, int ldc,
                                                 int do_relu,
                                                 const float* res,
                                                 float* Fout, int fcol, int fld,
                                                 const float2* rowscale,
                                                 int npmode,
                                                 int nrows) {
    constexpr int BM = 128, KC = 32, NG = BN / 64;
    __shared__ float As[KC][BM];
    __shared__ float Bs[KC][BN];
    int tid = threadIdx.x;
    int ty = tid >> 4, tx = tid & 15;
    int r0 = ty * 8;
    int rbase = blockIdx.x * BM;
    const float* B = (blockIdx.y == 0) ? B0 : (blockIdx.y == 1) ? B1 : B2;
    int ccol = npmode ? 0 : blockIdx.y * BN;

    unsigned long long acc[8][NG][2];
#pragma unroll
    for (int i = 0; i < 8; i++)
#pragma unroll
        for (int g = 0; g < NG; g++) { acc[i][g][0] = 0ull; acc[i][g][1] = 0ull; }

    for (int kk = 0; kk < K; kk += KC) {
#pragma unroll
        for (int i = 0; i < 4; i++) {
            int slot = tid + i * 256;
            int row = slot & 127, q = slot >> 7;
            float4 v = make_float4(0.f, 0.f, 0.f, 0.f);
            int gr = rbase + row;
            if (gr < nrows) {
                v = *(const float4*)(A + (size_t)gr * lda + kk + q * 4);
                if (rowscale) {
                    float2 sc = rowscale[gr];
                    float den = ((kk + q * 4) < 64) ? sc.x : sc.y;
                    float inv = __fdividef(1.f, den + 1e-9f);
                    v.x *= inv; v.y *= inv; v.z *= inv; v.w *= inv;
                }
            }
            As[q * 4 + 0][row] = v.x; As[q * 4 + 1][row] = v.y;
            As[q * 4 + 2][row] = v.z; As[q * 4 + 3][row] = v.w;
        }
#pragma unroll
        for (int i = 0; i < (KC * BN / 4) / 256; i++) {
            int slot = tid + i * 256;
            int kr = slot / (BN / 4), q = slot % (BN / 4);
            *(float4*)&Bs[kr][q * 4] = *(const float4*)(B + (size_t)(kk + kr) * BN + q * 4);
        }
        __syncthreads();
#pragma unroll
        for (int k = 0; k < KC; k++) {
            float4 a0 = *(const float4*)&As[k][r0];
            float4 a1 = *(const float4*)&As[k][r0 + 4];
            unsigned long long aa[8];
            aa[0] = dup2(a0.x); aa[1] = dup2(a0.y); aa[2] = dup2(a0.z); aa[3] = dup2(a0.w);
            aa[4] = dup2(a1.x); aa[5] = dup2(a1.y); aa[6] = dup2(a1.z); aa[7] = dup2(a1.w);
            unsigned long long bb[NG][2];
#pragma unroll
            for (int g = 0; g < NG; g++) {
                ulonglong2 t = *(const ulonglong2*)&Bs[k][g * 64 + tx * 4];
                bb[g][0] = t.x; bb[g][1] = t.y;
            }
#pragma unroll
            for (int i = 0; i < 8; i++)
#pragma unroll
                for (int g = 0; g < NG; g++) {
                    ffma2(acc[i][g][0], aa[i], bb[g][0]);
                    ffma2(acc[i][g][1], aa[i], bb[g][1]);
                }
        }
        __syncthreads();
    }
#pragma unroll
    for (int i = 0; i < 8; i++) {
        int gr = rbase + r0 + i;
        if (gr >= nrows) continue;
#pragma unroll
        for (int g = 0; g < NG; g++)
#pragma unroll
            for (int p = 0; p < 2; p++) {
                float2 v = unpk(acc[i][g][p]);
                int j = g * 64 + tx * 4 + p * 2;
                if (bias) { v.x += bias[j]; v.y += bias[j + 1]; }
                if (do_relu) { v.x = fmaxf(v.x, 0.f); v.y = fmaxf(v.y, 0.f); }
                if (res) { float2 rv = *(const float2*)(res + (size_t)gr * 64 + j); v.x += rv.x; v.y += rv.y; }
                if (npmode) {
                    if (blockIdx.y < 2)
                        *(__half2*)(g_NIJ + (size_t)gr * 256 + blockIdx.y * 128 + j) = __floats2half2_rn(v.x, v.y);
                    else
                        *(float2*)(C + (size_t)gr * ldc + j) = v;
                } else {
                    *(float2*)(C + (size_t)gr * ldc + ccol + j) = v;
                    if (Fout) *(float2*)(Fout + (size_t)gr * fld + fcol + j) = v;
                }
            }
    }
}

// ---------------- FUSED edge pass, dst-sorted, software-pipelined ----------------
__global__ __launch_bounds__(256) void k_edge(int l, const float* __restrict__ attnv) {
    __shared__ float sTe[7 * 128];
    __shared__ float sTr[31 * 128];
    int tid = threadIdx.x;
    for (int i = tid; i < 7 * 128;  i += 256) sTe[i] = g_TeP[l][i];
    for (int i = tid; i < 31 * 128; i += 256) sTr[i] = g_Tr[l][i];
    __syncthreads();

    int lane = tid & 31;
    int gw = (blockIdx.x * blockDim.x + tid) >> 5;
    int c = lane * 4;
    const float* Arc = g_Arc[l]; const float* Arp = g_Arp[l];
    float4 arc0 = *(const float4*)(Arc + c);
    float4 arc1 = *(const float4*)(Arc + 128 + c);
    float4 arp0 = *(const float4*)(Arp + c);
    float4 arp1 = *(const float4*)(Arp + 128 + c);
    float4 arp2 = *(const float4*)(Arp + 256 + c);
    float4 at   = *(const float4*)(attnv + c);

    int e0 = gw * CHUNK;
    if (e0 >= EE) return;
    int e1 = min(e0 + CHUNK, EE);

    // pipeline: records 2 ahead, gathers 1 ahead
    float4 A1 = __ldg(g_E1 + e0);
    uint4  A2 = __ldg(g_E2 + e0);
    int eB = min(e0 + 1, e1 - 1);
    float4 B1 = __ldg(g_E1 + eB);
    uint4  B2 = __ldg(g_E2 + eB);
    uint2  niA = __ldg((const uint2*)(g_NIJ + (size_t)A2.y * 256 + c));
    float4 npA = *(const float4*)(g_NPp + (size_t)A2.y * 128 + c);

    int cur = -1;
    float4 racc = make_float4(0.f, 0.f, 0.f, 0.f);
    float rs = 0.f;
    float4 nj = make_float4(0.f, 0.f, 0.f, 0.f);

    for (int e = e0; e < e1; e++) {
        int eC = min(e + 2, e1 - 1);
        float4 C1 = __ldg(g_E1 + eC);
        uint4  C2 = __ldg(g_E2 + eC);
        uint2  niB = __ldg((const uint2*)(g_NIJ + (size_t)B2.y * 256 + c));
        float4 npB = *(const float4*)(g_NPp + (size_t)B2.y * 128 + c);

        float rp2 = __uint_as_float(A2.x);
        int et = (int)(A2.z & 255u), rr = (int)(A2.z >> 8);
        int dd = (int)A2.w;
        if (dd != cur) {
            if (cur >= 0) {
                red_add_v4(g_hatt + (size_t)cur * 128 + c, racc.x, racc.y, racc.z, racc.w);
                float rso = __shfl_sync(0xffffffffu, rs, 16);
                if (lane == 0) red_add_v2(&g_s[(size_t)cur * 2], rs, rso);
            }
            cur = dd;
            racc = make_float4(0.f, 0.f, 0.f, 0.f);
            rs = 0.f;
            nj = nij4(__ldg((const uint2*)(g_NIJ + (size_t)dd * 256 + 128 + c)));
        }
        float4 te = *(const float4*)(sTe + et * 128 + c);
        float4 tr = *(const float4*)(sTr + rr * 128 + c);
        float4 ni = nij4(niA);
        float fx = ni.x + nj.x + te.x + tr.x + A1.x * arc0.x + A1.y * arc1.x + A1.z * arp0.x + A1.w * arp1.x + rp2 * arp2.x;
        float fy = ni.y + nj.y + te.y + tr.y + A1.x * arc0.y + A1.y * arc1.y + A1.z * arp0.y + A1.w * arp1.y + rp2 * arp2.y;
        float fz = ni.z + nj.z + te.z + tr.z + A1.x * arc0.z + A1.y * arc1.z + A1.z * arp0.z + A1.w * arp1.z + rp2 * arp2.z;
        float fw = ni.w + nj.w + te.w + tr.w + A1.x * arc0.w + A1.y * arc1.w + A1.z * arp0.w + A1.w * arp1.w + rp2 * arp2.w;
        float p;
        p  = (fx > 0.f ? fx : 0.2f * fx) * at.x;
        p += (fy > 0.f ? fy : 0.2f * fy) * at.y;
        p += (fz > 0.f ? fz : 0.2f * fz) * at.z;
        p += (fw > 0.f ? fw : 0.2f * fw) * at.w;
        p += __shfl_xor_sync(0xffffffffu, p, 1);
        p += __shfl_xor_sync(0xffffffffu, p, 2);
        p += __shfl_xor_sync(0xffffffffu, p, 4);
        p += __shfl_xor_sync(0xffffffffu, p, 8);
        float ex = __expf(p);
        racc.x += ex * npA.x; racc.y += ex * npA.y;
        racc.z += ex * npA.z; racc.w += ex * npA.w;
        rs += ex;

        A1 = B1; A2 = B2; B1 = C1; B2 = C2;
        niA = niB; npA = npB;
    }
    if (cur >= 0) {
        red_add_v4(g_hatt + (size_t)cur * 128 + c, racc.x, racc.y, racc.z, racc.w);
        float rso = __shfl_sync(0xffffffffu, rs, 16);
        if (lane == 0) red_add_v2(&g_s[(size_t)cur * 2], rs, rso);
    }
}

// ---------------- graph max pooling over d_out feature columns ----------------
__global__ __launch_bounds__(256) void k_pool(const float* __restrict__ out) {
    int g = blockIdx.y;
    int chunk = blockIdx.x;
    int t = threadIdx.x;
    int r_lo = chunk * 250, r_hi = r_lo + 250;
    float v0 = -3.4e38f, v1 = -3.4e38f;
    const float* base = out + (size_t)g * NPGX * OUTC;
    for (int r = r_lo; r < r_hi; r++) {
        const float* row = base + (size_t)r * OUTC;
        v0 = fmaxf(v0, row[t]);
        if (t < FDIM - 256) v1 = fmaxf(v1, row[256 + t]);
    }
    atomicMax(&g_gmaxU[g * FDIM + t], mono(v0));
    if (t < FDIM - 256) atomicMax(&g_gmaxU[g * FDIM + 256 + t], mono(v1));
}

// ---------------- fill rep half of output ----------------
__global__ __launch_bounds__(256) void k_rep(float2* __restrict__ out) {
    int idx = blockIdx.x * blockDim.x + threadIdx.x;     // float2 index over rep half
    const int HC = FDIM / 2;                             // 133
    const int TOT = NN * HC;
    if (idx >= TOT) return;
    int c2 = idx % HC;
    int rn = idx / HC;
    int g = rn / NPGX;
    float2 v;
    v.x = demono(g_gmaxU[g * FDIM + c2 * 2]);
    v.y = demono(g_gmaxU[g * FDIM + c2 * 2 + 1]);
    out[(size_t)rn * (OUTC / 2) + HC + c2] = v;
}

// ---------------- host ----------------
extern "C" void kernel_launch(void* const* d_in, const int* in_sizes, int n_in,
                              void* d_out, int out_size) {
    (void)in_sizes; (void)n_in; (void)out_size;
    const float* feat      = (const float*)d_in[0];
    const float* att_rc    = (const float*)d_in[1];
    const float* att_rp    = (const float*)d_in[2];
    const float* etype_emb = (const float*)d_in[3];
    const float* rid_emb   = (const float*)d_in[4];
    const float* rc_W      = (const float*)d_in[5];
    const float* rc_b      = (const float*)d_in[6];
    const float* rp_W      = (const float*)d_in[7];
    const float* rp_b      = (const float*)d_in[8];
    const float* fe_W0     = (const float*)d_in[9];
    const float* fe_b0     = (const float*)d_in[10];
    const float* fe_W1     = (const float*)d_in[11];
    const float* fe_b1     = (const float*)d_in[12];
    const float* W_ni      = (const float*)d_in[13];
    const float* W_nj      = (const float*)d_in[14];
    const float* W_fij     = (const float*)d_in[15];
    const float* W_node    = (const float*)d_in[16];
    const float* attn      = (const float*)d_in[17];
    const float* egat_bias = (const float*)d_in[18];
    const float* Wm0       = (const float*)d_in[19];
    const float* bm0       = (const float*)d_in[20];
    const float* Wm1       = (const float*)d_in[21];
    const float* bm1       = (const float*)d_in[22];
    const int*   src       = (const int*)d_in[23];
    const int*   dst       = (const int*)d_in[24];
    const int*   etype     = (const int*)d_in[25];
    const int*   rid       = (const int*)d_in[26];
    float* out = (float*)d_out;

    float *pH, *pT, *pNPp, *phatt, *ps;
    unsigned *pgmax;
    int *pcnt;
    cudaGetSymbolAddress((void**)&pH,    g_H);
    cudaGetSymbolAddress((void**)&pT,    g_T);
    cudaGetSymbolAddress((void**)&pNPp,  g_NPp);
    cudaGetSymbolAddress((void**)&phatt, g_hatt);
    cudaGetSymbolAddress((void**)&ps,    g_s);
    cudaGetSymbolAddress((void**)&pgmax, g_gmaxU);
    cudaGetSymbolAddress((void**)&pcnt,  g_cnt);

    const int GB = (NN + 127) / 128;
    const int EB = (EE + 255) / 256;

    // ---- one-time edge sort by dst ----
    cudaMemsetAsync(pcnt, 0, NN * sizeof(int));
    k_hist<<<EB, 256>>>(dst);
    k_scan<<<1, 1024>>>();
    k_scatter<<<EB, 256>>>(src, dst, etype, rid, att_rc, att_rp);

    k_feat1<<<GB, 128>>>(feat, fe_W0, fe_b0, out);
    k_tables<<<3, 256>>>(etype_emb, rid_emb, rc_W, rc_b, rp_W, rp_b, W_fij, egat_bias);
    // h0 = T@W1 + b1 ; also writes out[:,10:74]
    k_gemm<64, 64><<<dim3(GB, 1), 256>>>(pT, 128, fe_W1, nullptr, nullptr, fe_b1,
                                         pH, 64, 0, nullptr, out, 10, OUTC, nullptr, 0, NN);

    for (int l = 0; l < 3; l++) {
        cudaMemsetAsync(phatt, 0, (size_t)NN * 128 * sizeof(float));
        cudaMemsetAsync(ps,    0, (size_t)NN * 2 * sizeof(float));
        // npmode: y0->NIJ[0:128] fp16, y1->NIJ[128:256] fp16, y2->NPp fp32
        k_gemm<64, 128><<<dim3(GB, 3), 256>>>(pH, 64,
                                              W_ni + (size_t)l * 64 * 128,
                                              W_nj + (size_t)l * 64 * 128,
                                              W_node + (size_t)l * 64 * 128,
                                              nullptr, pNPp, 128, 0, nullptr, nullptr, 0, 0, nullptr, 1, NN);
        k_edge<<<(EE / CHUNK + 7) / 8, 256>>>(l, attn + (size_t)l * 128);
        k_gemm<128, 128><<<dim3(GB, 1), 256>>>(phatt, 128,
                                               Wm0 + (size_t)l * 128 * 128, nullptr, nullptr,
                                               bm0 + (size_t)l * 128,
                                               pT, 128, 1, nullptr, nullptr, 0, 0, (const float2*)ps, 0, NN);
        k_gemm<128, 64><<<dim3(GB, 1), 256>>>(pT, 128,
                                              Wm1 + (size_t)l * 128 * 64, nullptr, nullptr,
                                              bm1 + (size_t)l * 64,
                                              pH, 64, 0, pH, out, 10 + 64 * (l + 1), OUTC, nullptr, 0, NN);
    }
    cudaMemsetAsync(pgmax, 0, (size_t)NB * FDIM * sizeof(unsigned));
    k_pool<<<dim3(25, NB), 256>>>(out);
    k_rep<<<(NN * (FDIM / 2) + 255) / 256, 256>>>((float2*)out);
}